// round 6
// baseline (speedup 1.0000x reference)
#include <cuda_runtime.h>
#include <cuda_bf16.h>
#include <cuda_fp16.h>
#include <math.h>
#include <stdint.h>

// ---------------------------------------------------------------------------
// Problem constants
// ---------------------------------------------------------------------------
#define T_TOK   1024
#define HID     2880
#define NH      64
#define KVH     8
#define HD      64
#define INTER   2880
#define QKV_DIM (HD*(NH+2*KVH))      // 5120
#define O_DIM   (NH*HD)              // 4096
#define U_DIM   (2*INTER)            // 5760
#define SM_SCALE 0.125f
#define EPSF    1e-5f

#define NPAD_OUT 3072
#define NPAD_UP  5888
#define NPAD_DN  3072

// ---------------------------------------------------------------------------
// Scratch
// ---------------------------------------------------------------------------
__device__ float g_qkv[T_TOK * QKV_DIM];
__device__ float g_h  [T_TOK * HID];
__device__ float g_u  [T_TOK * U_DIM];

// weights: fp16 hi only, row stride K
__device__ __align__(256) __half g_w_qkv[QKV_DIM * HID];
__device__ __align__(256) __half g_w_out[NPAD_OUT * O_DIM];
__device__ __align__(256) __half g_w_up [NPAD_UP  * HID];
__device__ __align__(256) __half g_w_dn [NPAD_DN  * INTER];
// activations: fp16 [hi(0..K) | lo(K..2K)], row stride 2K
__device__ __align__(256) __half g_a2   [T_TOK * 2 * O_DIM];

// ---------------------------------------------------------------------------
// PTX helpers
// ---------------------------------------------------------------------------
__device__ __forceinline__ uint32_t smem_u32(const void* p) {
    uint32_t a;
    asm("{ .reg .u64 t; cvta.to.shared.u64 t, %1; cvt.u32.u64 %0, t; }" : "=r"(a) : "l"(p));
    return a;
}
__device__ __forceinline__ void cp16(uint32_t dst, const void* src) {
    asm volatile("cp.async.cg.shared.global [%0], [%1], 16;" :: "r"(dst), "l"(src));
}
__device__ __forceinline__ void cp_commit() {
    asm volatile("cp.async.commit_group;" ::: "memory");
}
__device__ __forceinline__ void cp_wait1() {
    asm volatile("cp.async.wait_group 1;" ::: "memory");
}
__device__ __forceinline__ void cp_wait0() {
    asm volatile("cp.async.wait_group 0;" ::: "memory");
}
__device__ __forceinline__ void ldmatrix_x4(uint32_t& r0, uint32_t& r1,
                                            uint32_t& r2, uint32_t& r3, uint32_t addr) {
    asm volatile("ldmatrix.sync.aligned.m8n8.x4.shared.b16 {%0,%1,%2,%3}, [%4];"
        : "=r"(r0), "=r"(r1), "=r"(r2), "=r"(r3) : "r"(addr));
}
__device__ __forceinline__ void mma_f16(float& c0, float& c1, float& c2, float& c3,
                                        uint32_t a0, uint32_t a1, uint32_t a2, uint32_t a3,
                                        uint32_t b0, uint32_t b1) {
    asm volatile("mma.sync.aligned.m16n8k16.row.col.f32.f16.f16.f32 "
        "{%0,%1,%2,%3}, {%4,%5,%6,%7}, {%8,%9}, {%0,%1,%2,%3};"
        : "+f"(c0), "+f"(c1), "+f"(c2), "+f"(c3)
        : "r"(a0), "r"(a1), "r"(a2), "r"(a3), "r"(b0), "r"(b1));
}
__device__ __forceinline__ void mma_tf32(float* c, const uint32_t* a, const uint32_t* b) {
    asm volatile("mma.sync.aligned.m16n8k8.row.col.f32.tf32.tf32.f32 "
        "{%0,%1,%2,%3}, {%4,%5,%6,%7}, {%8,%9}, {%0,%1,%2,%3};"
        : "+f"(c[0]), "+f"(c[1]), "+f"(c[2]), "+f"(c[3])
        : "r"(a[0]), "r"(a[1]), "r"(a[2]), "r"(a[3]), "r"(b[0]), "r"(b[1]));
}
__device__ __forceinline__ float tf32r(float x) {
    uint32_t o;
    asm("cvt.rna.tf32.f32 %0, %1;" : "=r"(o) : "f"(x));
    return __uint_as_float(o);
}

// FMA-pipe exp
__device__ __forceinline__ float fast_exp(float x) {
    x = fmaxf(x, -80.f);
    const float y = x * 1.4426950408889634f;
    const float fn = y + 12582912.f;
    const int ni = __float_as_int(fn) - 0x4B400000;
    const float f = y - (fn - 12582912.f);
    float p = 1.3333558146e-3f;
    p = fmaf(p, f, 9.6181291076e-3f);
    p = fmaf(p, f, 5.5504108664e-2f);
    p = fmaf(p, f, 2.4022650696e-1f);
    p = fmaf(p, f, 6.9314718056e-1f);
    p = fmaf(p, f, 1.0f);
    return p * __int_as_float((ni + 127) << 23);
}

__device__ __forceinline__ void store_split2h(__half* dst2, size_t stride2,
                                              int m, int khalf, int col,
                                              float v0, float v1) {
    __half h0 = __float2half_rn(v0), h1 = __float2half_rn(v1);
    float l0 = v0 - __half2float(h0), l1 = v1 - __half2float(h1);
    *(__half2*)(dst2 + (size_t)m * stride2 + col) = __halves2half2(h0, h1);
    *(__half2*)(dst2 + (size_t)m * stride2 + khalf + col) = __floats2half2_rn(l0, l1);
}

// ---------------------------------------------------------------------------
// fp32 -> fp16 weight conversion. Rows >= Nrows zeroed.
// ---------------------------------------------------------------------------
__global__ __launch_bounds__(256) void convert_h_kernel(
    const float* __restrict__ X, __half* __restrict__ Xh,
    int Nrows, int K, int Npad)
{
    const long long idx = (long long)blockIdx.x * 256 + threadIdx.x;
    const int kq = K >> 2;
    const long long total = (long long)Npad * kq;
    if (idx >= total) return;
    const int n = (int)(idx / kq);
    const int k = (int)(idx - (long long)n * kq) * 4;
    float4 v = make_float4(0.f, 0.f, 0.f, 0.f);
    if (n < Nrows) v = *(const float4*)(X + (size_t)n * K + k);
    __half2* p = (__half2*)(Xh + (size_t)n * K + k);
    p[0] = __floats2half2_rn(v.x, v.y);
    p[1] = __floats2half2_rn(v.z, v.w);
}

// ---------------------------------------------------------------------------
// Split-fp16 GEMM (2 passes: Ah*Wh + Al*Wh) via mma.sync
// 128x256 CTA tile, BK=64, double-buffered cp.async.
// A row stride 2K (hi|lo), W row stride K (hi only).
// ---------------------------------------------------------------------------
#define KSTRIDE_B 144
#define ATILE_B  (128 * KSTRIDE_B)
#define BTILE_B  (256 * KSTRIDE_B)
#define GSMEM_TOTAL (2 * ATILE_B + 2 * BTILE_B)

__device__ __forceinline__ void fill_tiles_mma(
    uint32_t aT, uint32_t bT,
    const __half* __restrict__ A2, const __half* __restrict__ W,
    int Kp, int Kw, int m0, int n0, int ka, int kw, int tid)
{
    #pragma unroll
    for (int i = 0; i < 4; i++) {
        int q = tid + 256 * i;
        int r = q >> 3, c = q & 7;
        cp16(aT + r * KSTRIDE_B + c * 16, A2 + (size_t)(m0 + r) * Kp + ka + c * 8);
    }
    #pragma unroll
    for (int i = 0; i < 8; i++) {
        int q = tid + 256 * i;
        int r = q >> 3, c = q & 7;
        cp16(bT + r * KSTRIDE_B + c * 16, W + (size_t)(n0 + r) * Kw + kw + c * 8);
    }
}

template<bool RES>
__global__ __launch_bounds__(256) void mma_gemm(
    const __half* __restrict__ A2, const __half* __restrict__ W,
    const float* __restrict__ bias, const float* __restrict__ res,
    float* __restrict__ C, int K, int Nout)
{
    extern __shared__ char smem[];
    const uint32_t sbase = smem_u32(smem);
    const uint32_t tA[2] = { sbase,                sbase + ATILE_B };
    const uint32_t tB[2] = { sbase + 2 * ATILE_B,  sbase + 2 * ATILE_B + BTILE_B };

    const int tid  = threadIdx.x;
    const int wid  = tid >> 5;
    const int lane = tid & 31;
    const int wm   = wid >> 2;
    const int wn   = wid & 3;
    const int m0 = blockIdx.x * 128;
    const int n0 = blockIdx.y * 256;
    const int Kp = 2 * K;
    const int NCseg = K >> 6;
    const int NC = 2 * NCseg;

    const uint32_t aOff = (uint32_t)((wm * 64 + (lane & 15)) * KSTRIDE_B + (lane >> 4) * 16);
    const uint32_t bOff = (uint32_t)((wn * 64 + (lane & 7) + ((lane >> 4) & 1) * 8) * KSTRIDE_B
                                     + ((lane >> 3) & 1) * 16);

    float acc[4][8][4];
    #pragma unroll
    for (int i = 0; i < 4; i++)
        #pragma unroll
        for (int j = 0; j < 8; j++)
            #pragma unroll
            for (int q = 0; q < 4; q++) acc[i][j][q] = 0.f;

    fill_tiles_mma(tA[0], tB[0], A2, W, Kp, K, m0, n0, 0, 0, tid);
    cp_commit();

    for (int c = 0; c < NC; c++) {
        const int b = c & 1;
        if (c + 1 < NC) {
            const int nb = (c + 1) & 1;
            const int cn = c + 1;
            const int seg = (cn >= NCseg) ? 1 : 0;
            const int kk = (cn - seg * NCseg) << 6;
            fill_tiles_mma(tA[nb], tB[nb], A2, W, Kp, K, m0, n0,
                           seg * K + kk, kk, tid);
            cp_commit();
            cp_wait1();
        } else {
            cp_wait0();
        }
        __syncthreads();

        #pragma unroll
        for (int ks = 0; ks < 4; ks++) {
            const uint32_t kb = (uint32_t)(ks * 32);
            uint32_t a[4][4];
            #pragma unroll
            for (int mf = 0; mf < 4; mf++)
                ldmatrix_x4(a[mf][0], a[mf][1], a[mf][2], a[mf][3],
                            tA[b] + aOff + mf * 16 * KSTRIDE_B + kb);
            uint32_t bb[8][2];
            #pragma unroll
            for (int bf = 0; bf < 4; bf++) {
                uint32_t r0, r1, r2, r3;
                ldmatrix_x4(r0, r1, r2, r3,
                            tB[b] + bOff + bf * 16 * KSTRIDE_B + kb);
                bb[bf * 2 + 0][0] = r0; bb[bf * 2 + 0][1] = r1;
                bb[bf * 2 + 1][0] = r2; bb[bf * 2 + 1][1] = r3;
            }
            #pragma unroll
            for (int mf = 0; mf < 4; mf++)
                #pragma unroll
                for (int nf = 0; nf < 8; nf++)
                    mma_f16(acc[mf][nf][0], acc[mf][nf][1],
                            acc[mf][nf][2], acc[mf][nf][3],
                            a[mf][0], a[mf][1], a[mf][2], a[mf][3],
                            bb[nf][0], bb[nf][1]);
        }
        __syncthreads();
    }

    const int g = lane >> 2;
    const int t = lane & 3;
    #pragma unroll
    for (int nf = 0; nf < 8; nf++) {
        const int col = n0 + wn * 64 + nf * 8 + t * 2;
        if (col >= Nout) continue;
        const float bx = bias[col], by = bias[col + 1];
        #pragma unroll
        for (int mf = 0; mf < 4; mf++) {
            const int r0 = m0 + wm * 64 + mf * 16 + g;
            float2 v0 = make_float2(acc[mf][nf][0] + bx, acc[mf][nf][1] + by);
            float2 v1 = make_float2(acc[mf][nf][2] + bx, acc[mf][nf][3] + by);
            if (RES) {
                const float2 q0 = *(const float2*)(res + (size_t)r0 * Nout + col);
                const float2 q1 = *(const float2*)(res + (size_t)(r0 + 8) * Nout + col);
                v0.x += q0.x; v0.y += q0.y; v1.x += q1.x; v1.y += q1.y;
            }
            *(float2*)(C + (size_t)r0 * Nout + col) = v0;
            *(float2*)(C + (size_t)(r0 + 8) * Nout + col) = v1;
        }
    }
}

// ---------------------------------------------------------------------------
// RMSNorm -> split-fp16 (fused)
// ---------------------------------------------------------------------------
__global__ __launch_bounds__(256) void rmsnorm_split_kernel(
    const float* __restrict__ x, const float* __restrict__ scale,
    __half* __restrict__ a2)
{
    const int row = blockIdx.x;
    const float* xr = x + (size_t)row * HID;
    float s = 0.f;
    for (int i = threadIdx.x; i < HID; i += 256) { float v = xr[i]; s += v * v; }
    __shared__ float red[256];
    red[threadIdx.x] = s;
    __syncthreads();
    for (int off = 128; off > 0; off >>= 1) {
        if (threadIdx.x < off) red[threadIdx.x] += red[threadIdx.x + off];
        __syncthreads();
    }
    const float inv = rsqrtf(red[0] / (float)HID + EPSF);
    __half* rowp = a2 + (size_t)row * 2 * HID;
    for (int i = threadIdx.x * 2; i < HID; i += 512) {
        float v0 = xr[i] * inv * scale[i];
        float v1 = xr[i + 1] * inv * scale[i + 1];
        __half h0 = __float2half_rn(v0), h1 = __float2half_rn(v1);
        *(__half2*)(rowp + i) = __halves2half2(h0, h1);
        *(__half2*)(rowp + HID + i) = __floats2half2_rn(
            v0 - __half2float(h0), v1 - __half2float(h1));
    }
}

// ---------------------------------------------------------------------------
// RoPE
// ---------------------------------------------------------------------------
__global__ void rope_kernel(float* __restrict__ qkv)
{
    const int t = blockIdx.x;
    const int head = blockIdx.y;
    const int i = threadIdx.x;

    float* base;
    if (head < NH) base = qkv + (size_t)t * QKV_DIM + head * HD;
    else           base = qkv + (size_t)t * QKV_DIM + NH * HD + (head - NH) * HD;

    const float PI = 3.14159265358979323846f;
    const float rope_base = 150000.f;
    const float freq = powf(rope_base, (float)i / 32.f);
    const float conc = 0.1f * logf(32.f) + 1.f;
    const float lg = logf(rope_base);
    const float low  = 32.f * logf(4096.f / (32.f * 2.f * PI)) / lg;
    const float high = 32.f * logf(4096.f / (2.f * PI)) / lg;
    const float interp = 1.f / (32.f * freq);
    const float extrap = 1.f / freq;
    float ramp = ((float)i - low) / (high - low);
    ramp = fminf(fmaxf(ramp, 0.f), 1.f);
    const float mask = 1.f - ramp;
    const float invf = interp * (1.f - mask) + extrap * mask;
    const float ang = (float)t * invf;
    const float c = cosf(ang) * conc;
    const float s = sinf(ang) * conc;

    const float x1 = base[i];
    const float x2 = base[i + 32];
    base[i]      = x1 * c - x2 * s;
    base[i + 32] = x2 * c + x1 * s;
}

// ---------------------------------------------------------------------------
// Causal GQA flash attention (tf32 mma + FMA-pipe exp), split-fp16 output
// ---------------------------------------------------------------------------
#define ATQ 68
#define ATV 72
#define ATTN_SMEM ((3 * 64 * ATQ + 64 * ATV + 3 * 64 + 2 * 256) * (int)sizeof(float))

__global__ __launch_bounds__(256) void attn_mma_kernel(
    const float* __restrict__ qkv, __half* __restrict__ o2)
{
    extern __shared__ float sm[];
    float* Qs   = sm;
    float* Ks   = Qs + 64 * ATQ;
    float* Ss   = Ks + 64 * ATQ;
    float* Vs   = Ss + 64 * ATQ;
    float* mrow = Vs + 64 * ATV;
    float* lrow = mrow + 64;
    float* arow = lrow + 64;
    float* pm   = arow + 64;
    float* ps   = pm + 256;

    const int qt = blockIdx.x, h = blockIdx.y, kh = h >> 3;
    const int tid = threadIdx.x, wid = tid >> 5, lane = tid & 31;
    const int wm = wid >> 2, wn = wid & 3;
    const int g = lane >> 2, qd = lane & 3;
    const int sr = tid & 63, sq = tid >> 6;

    for (int i = tid; i < 64 * 64; i += 256) {
        int r = i >> 6, d = i & 63;
        Qs[r * ATQ + d] = tf32r(qkv[(size_t)(qt * 64 + r) * QKV_DIM + h * HD + d]);
    }
    if (tid < 64) { mrow[tid] = -1e30f; lrow[tid] = 0.f; }
    float o[2][2][4];
    #pragma unroll
    for (int i = 0; i < 2; i++)
        #pragma unroll
        for (int j = 0; j < 2; j++)
            #pragma unroll
            for (int q = 0; q < 4; q++) o[i][j][q] = 0.f;
    __syncthreads();

    for (int kt = 0; kt <= qt; kt++) {
        for (int i = tid; i < 64 * 64; i += 256) {
            int r = i >> 6, d = i & 63;
            size_t base = (size_t)(kt * 64 + r) * QKV_DIM;
            Ks[r * ATQ + d] = tf32r(qkv[base + NH * HD + kh * HD + d]);
            Vs[r * ATV + d] = tf32r(qkv[base + (NH + KVH) * HD + kh * HD + d]);
        }
        __syncthreads();

        float s[2][2][4];
        #pragma unroll
        for (int i = 0; i < 2; i++)
            #pragma unroll
            for (int j = 0; j < 2; j++)
                #pragma unroll
                for (int q = 0; q < 4; q++) s[i][j][q] = 0.f;
        #pragma unroll
        for (int k8 = 0; k8 < 8; k8++) {
            const int k0 = k8 * 8;
            uint32_t a[2][4], b[2][2];
            #pragma unroll
            for (int mf = 0; mf < 2; mf++) {
                const int rb = wm * 32 + mf * 16;
                a[mf][0] = __float_as_uint(Qs[(rb + g) * ATQ + k0 + qd]);
                a[mf][1] = __float_as_uint(Qs[(rb + g + 8) * ATQ + k0 + qd]);
                a[mf][2] = __float_as_uint(Qs[(rb + g) * ATQ + k0 + 4 + qd]);
                a[mf][3] = __float_as_uint(Qs[(rb + g + 8) * ATQ + k0 + 4 + qd]);
            }
            #pragma unroll
            for (int nf = 0; nf < 2; nf++) {
                const int nb = wn * 16 + nf * 8;
                b[nf][0] = __float_as_uint(Ks[(nb + g) * ATQ + k0 + qd]);
                b[nf][1] = __float_as_uint(Ks[(nb + g) * ATQ + k0 + 4 + qd]);
            }
            #pragma unroll
            for (int mf = 0; mf < 2; mf++)
                #pragma unroll
                for (int nf = 0; nf < 2; nf++)
                    mma_tf32(s[mf][nf], a[mf], b[nf]);
        }
        #pragma unroll
        for (int mf = 0; mf < 2; mf++)
            #pragma unroll
            for (int nf = 0; nf < 2; nf++) {
                const int r0 = wm * 32 + mf * 16 + g;
                const int c0 = wn * 16 + nf * 8 + 2 * qd;
                *(float2*)&Ss[r0 * ATQ + c0] =
                    make_float2(s[mf][nf][0] * SM_SCALE, s[mf][nf][1] * SM_SCALE);
                *(float2*)&Ss[(r0 + 8) * ATQ + c0] =
                    make_float2(s[mf][nf][2] * SM_SCALE, s[mf][nf][3] * SM_SCALE);
            }
        __syncthreads();

        {
            const int cmax = (kt == qt) ? (sr + 1) : 64;
            const int c0 = sq * 16;
            float mx = -1e30f;
            #pragma unroll
            for (int c = c0; c < c0 + 16; c++)
                if (c < cmax) mx = fmaxf(mx, Ss[sr * ATQ + c]);
            pm[sq * 64 + sr] = mx;
            __syncthreads();
            const float mold = mrow[sr];
            const float mfin = fmaxf(mold,
                fmaxf(fmaxf(pm[sr], pm[64 + sr]), fmaxf(pm[128 + sr], pm[192 + sr])));
            float sum = 0.f;
            #pragma unroll
            for (int c = c0; c < c0 + 16; c++) {
                float p = (c < cmax) ? fast_exp(Ss[sr * ATQ + c] - mfin) : 0.f;
                Ss[sr * ATQ + c] = tf32r(p);
                sum += p;
            }
            ps[sq * 64 + sr] = sum;
            __syncthreads();
            if (sq == 0) {
                const float alpha = fast_exp(mold - mfin);
                mrow[sr] = mfin;
                lrow[sr] = lrow[sr] * alpha
                         + ps[sr] + ps[64 + sr] + ps[128 + sr] + ps[192 + sr];
                arow[sr] = alpha;
            }
            __syncthreads();
        }

        #pragma unroll
        for (int mf = 0; mf < 2; mf++) {
            const int r0 = wm * 32 + mf * 16 + g;
            const float al0 = arow[r0], al1 = arow[r0 + 8];
            #pragma unroll
            for (int nf = 0; nf < 2; nf++) {
                o[mf][nf][0] *= al0; o[mf][nf][1] *= al0;
                o[mf][nf][2] *= al1; o[mf][nf][3] *= al1;
            }
        }
        #pragma unroll
        for (int k8 = 0; k8 < 8; k8++) {
            const int k0 = k8 * 8;
            uint32_t a[2][4], b[2][2];
            #pragma unroll
            for (int mf = 0; mf < 2; mf++) {
                const int rb = wm * 32 + mf * 16;
                a[mf][0] = __float_as_uint(Ss[(rb + g) * ATQ + k0 + qd]);
                a[mf][1] = __float_as_uint(Ss[(rb + g + 8) * ATQ + k0 + qd]);
                a[mf][2] = __float_as_uint(Ss[(rb + g) * ATQ + k0 + 4 + qd]);
                a[mf][3] = __float_as_uint(Ss[(rb + g + 8) * ATQ + k0 + 4 + qd]);
            }
            #pragma unroll
            for (int nf = 0; nf < 2; nf++) {
                const int nb = wn * 16 + nf * 8;
                b[nf][0] = __float_as_uint(Vs[(k0 + qd) * ATV + nb + g]);
                b[nf][1] = __float_as_uint(Vs[(k0 + 4 + qd) * ATV + nb + g]);
            }
            #pragma unroll
            for (int mf = 0; mf < 2; mf++)
                #pragma unroll
                for (int nf = 0; nf < 2; nf++)
                    mma_tf32(o[mf][nf], a[mf], b[nf]);
        }
        __syncthreads();
    }

    #pragma unroll
    for (int mf = 0; mf < 2; mf++) {
        const int r0 = wm * 32 + mf * 16 + g;
        const float li0 = 1.f / lrow[r0];
        const float li1 = 1.f / lrow[r0 + 8];
        #pragma unroll
        for (int nf = 0; nf < 2; nf++) {
            const int col = h * HD + wn * 16 + nf * 8 + 2 * qd;
            store_split2h(o2, 2 * O_DIM, qt * 64 + r0, O_DIM, col,
                          o[mf][nf][0] * li0, o[mf][nf][1] * li0);
            store_split2h(o2, 2 * O_DIM, qt * 64 + r0 + 8, O_DIM, col,
                          o[mf][nf][2] * li1, o[mf][nf][3] * li1);
        }
    }
}

// ---------------------------------------------------------------------------
// Clamped SwiGLU -> split-fp16 (fused)
// ---------------------------------------------------------------------------
__global__ __launch_bounds__(256) void act_split_kernel(
    const float* __restrict__ u, __half* __restrict__ a2)
{
    const int idx = blockIdx.x * 256 + threadIdx.x;
    if (idx >= T_TOK * INTER) return;
    const int row = idx / INTER, col = idx - row * INTER;
    float gx  = u[(size_t)row * U_DIM + 2 * col];
    float lin = u[(size_t)row * U_DIM + 2 * col + 1];
    gx  = fminf(gx, 7.f);
    lin = fminf(fmaxf(lin, -7.f), 7.f);
    const float sg = 1.f / (1.f + fast_exp(-1.702f * gx));
    const float v = gx * sg * (lin + 1.f);
    __half hi = __float2half_rn(v);
    a2[(size_t)row * 2 * INTER + col] = hi;
    a2[(size_t)row * 2 * INTER + INTER + col] =
        __float2half_rn(v - __half2float(hi));
}

// ---------------------------------------------------------------------------
// Launch
// ---------------------------------------------------------------------------
static inline int cdiv_ll(long long a, int b) { return (int)((a + b - 1) / b); }

extern "C" void kernel_launch(void* const* d_in, const int* in_sizes, int n_in,
                              void* d_out, int out_size)
{
    const float* x        = (const float*)d_in[0];
    const float* an_scale = (const float*)d_in[1];
    const float* wqkv     = (const float*)d_in[2];
    const float* bqkv     = (const float*)d_in[3];
    const float* wout     = (const float*)d_in[4];
    const float* bout     = (const float*)d_in[5];
    const float* mn_scale = (const float*)d_in[6];
    const float* w1       = (const float*)d_in[7];
    const float* b1       = (const float*)d_in[8];
    const float* w2       = (const float*)d_in[9];
    const float* b2       = (const float*)d_in[10];
    float* out = (float*)d_out;

    static float *qkv_p = nullptr, *h_p, *u_p;
    static __half *wqkv_h, *wout_h, *wup_h, *wdn_h, *a2_p;
    if (!qkv_p) {
        cudaGetSymbolAddress((void**)&qkv_p,  g_qkv);
        cudaGetSymbolAddress((void**)&h_p,    g_h);
        cudaGetSymbolAddress((void**)&u_p,    g_u);
        cudaGetSymbolAddress((void**)&wqkv_h, g_w_qkv);
        cudaGetSymbolAddress((void**)&wout_h, g_w_out);
        cudaGetSymbolAddress((void**)&wup_h,  g_w_up);
        cudaGetSymbolAddress((void**)&wdn_h,  g_w_dn);
        cudaGetSymbolAddress((void**)&a2_p,   g_a2);
    }
    cudaFuncSetAttribute(attn_mma_kernel,
                         cudaFuncAttributeMaxDynamicSharedMemorySize, ATTN_SMEM);
    cudaFuncSetAttribute(mma_gemm<false>,
                         cudaFuncAttributeMaxDynamicSharedMemorySize, GSMEM_TOTAL);
    cudaFuncSetAttribute(mma_gemm<true>,
                         cudaFuncAttributeMaxDynamicSharedMemorySize, GSMEM_TOTAL);

    // Weight conversions (fp16 hi only)
    convert_h_kernel<<<cdiv_ll((long long)QKV_DIM * HID / 4, 256), 256>>>(
        wqkv, wqkv_h, QKV_DIM, HID, QKV_DIM);
    convert_h_kernel<<<cdiv_ll((long long)NPAD_OUT * O_DIM / 4, 256), 256>>>(
        wout, wout_h, HID, O_DIM, NPAD_OUT);
    convert_h_kernel<<<cdiv_ll((long long)NPAD_UP * HID / 4, 256), 256>>>(
        w1, wup_h, U_DIM, HID, NPAD_UP);
    convert_h_kernel<<<cdiv_ll((long long)NPAD_DN * INTER / 4, 256), 256>>>(
        w2, wdn_h, HID, INTER, NPAD_DN);

    // 1) attn rmsnorm -> split a2
    rmsnorm_split_kernel<<<T_TOK, 256>>>(x, an_scale, a2_p);

    // 2) QKV GEMM
    {
        dim3 grid(T_TOK / 128, QKV_DIM / 256);
        mma_gemm<false><<<grid, 256, GSMEM_TOTAL>>>(a2_p, wqkv_h, bqkv, nullptr,
                                                    qkv_p, HID, QKV_DIM);
    }

    // 3) RoPE
    {
        dim3 grid(T_TOK, NH + KVH);
        rope_kernel<<<grid, 32>>>(qkv_p);
    }

    // 4) attention (writes split a2, K=4096)
    {
        dim3 grid(T_TOK / 64, NH);
        attn_mma_kernel<<<grid, 256, ATTN_SMEM>>>(qkv_p, a2_p);
    }

    // 5) out GEMM + residual
    {
        dim3 grid(T_TOK / 128, NPAD_OUT / 256);
        mma_gemm<true><<<grid, 256, GSMEM_TOTAL>>>(a2_p, wout_h, bout, x,
                                                   h_p, O_DIM, HID);
    }

    // 6) mlp rmsnorm -> split a2
    rmsnorm_split_kernel<<<T_TOK, 256>>>(h_p, mn_scale, a2_p);

    // 7) MLP up GEMM
    {
        dim3 grid(T_TOK / 128, NPAD_UP / 256);
        mma_gemm<false><<<grid, 256, GSMEM_TOTAL>>>(a2_p, wup_h, b1, nullptr,
                                                    u_p, HID, U_DIM);
    }

    // 8) activation -> split a2
    act_split_kernel<<<(T_TOK * INTER + 255) / 256, 256>>>(u_p, a2_p);

    // 9) MLP down GEMM + residual -> out
    {
        dim3 grid(T_TOK / 128, NPAD_DN / 256);
        mma_gemm<true><<<grid, 256, GSMEM_TOTAL>>>(a2_p, wdn_h, b2, h_p,
                                                   out, INTER, HID);
    }
}

// round 7
// speedup vs baseline: 1.4703x; 1.4703x over previous
#include <cuda_runtime.h>
#include <cuda_bf16.h>
#include <math.h>
#include <stdint.h>

// ---------------------------------------------------------------------------
// Problem constants
// ---------------------------------------------------------------------------
#define T_TOK   1024
#define HID     2880
#define NH      64
#define KVH     8
#define HD      64
#define INTER   2880
#define QKV_DIM (HD*(NH+2*KVH))      // 5120
#define O_DIM   (NH*HD)              // 4096
#define U_DIM   (2*INTER)            // 5760
#define SM_SCALE 0.125f
#define EPSF    1e-5f

#define NPAD_OUT 3072
#define NPAD_UP  5888
#define NPAD_DN  3072

// ---------------------------------------------------------------------------
// Scratch
// ---------------------------------------------------------------------------
__device__ float g_qkv[T_TOK * QKV_DIM];
__device__ float g_h  [T_TOK * HID];
__device__ float g_u  [T_TOK * U_DIM];
__device__ float g_ws [3 * T_TOK * NPAD_UP];     // split-K partials (max Npad)

// split-bf16: row layout [hi(0..K-1) | lo(K..2K-1)], row stride 2K
__device__ __align__(256) __nv_bfloat16 g_w2_qkv[QKV_DIM * 2 * HID];
__device__ __align__(256) __nv_bfloat16 g_w2_out[NPAD_OUT * 2 * O_DIM];
__device__ __align__(256) __nv_bfloat16 g_w2_up [NPAD_UP  * 2 * HID];
__device__ __align__(256) __nv_bfloat16 g_w2_dn [NPAD_DN  * 2 * INTER];
__device__ __align__(256) __nv_bfloat16 g_a2    [T_TOK * 2 * O_DIM];

// ---------------------------------------------------------------------------
// PTX helpers
// ---------------------------------------------------------------------------
__device__ __forceinline__ uint32_t smem_u32(const void* p) {
    uint32_t a;
    asm("{ .reg .u64 t; cvta.to.shared.u64 t, %1; cvt.u32.u64 %0, t; }" : "=r"(a) : "l"(p));
    return a;
}
__device__ __forceinline__ void cp16(uint32_t dst, const void* src) {
    asm volatile("cp.async.cg.shared.global [%0], [%1], 16;" :: "r"(dst), "l"(src));
}
__device__ __forceinline__ void cp_commit() {
    asm volatile("cp.async.commit_group;" ::: "memory");
}
__device__ __forceinline__ void cp_wait1() {
    asm volatile("cp.async.wait_group 1;" ::: "memory");
}
__device__ __forceinline__ void cp_wait0() {
    asm volatile("cp.async.wait_group 0;" ::: "memory");
}
__device__ __forceinline__ void ldmatrix_x4(uint32_t& r0, uint32_t& r1,
                                            uint32_t& r2, uint32_t& r3, uint32_t addr) {
    asm volatile("ldmatrix.sync.aligned.m8n8.x4.shared.b16 {%0,%1,%2,%3}, [%4];"
        : "=r"(r0), "=r"(r1), "=r"(r2), "=r"(r3) : "r"(addr));
}
__device__ __forceinline__ void mma_bf16(float& c0, float& c1, float& c2, float& c3,
                                         uint32_t a0, uint32_t a1, uint32_t a2, uint32_t a3,
                                         uint32_t b0, uint32_t b1) {
    asm volatile("mma.sync.aligned.m16n8k16.row.col.f32.bf16.bf16.f32 "
        "{%0,%1,%2,%3}, {%4,%5,%6,%7}, {%8,%9}, {%0,%1,%2,%3};"
        : "+f"(c0), "+f"(c1), "+f"(c2), "+f"(c3)
        : "r"(a0), "r"(a1), "r"(a2), "r"(a3), "r"(b0), "r"(b1));
}
__device__ __forceinline__ void mma_tf32(float* c, const uint32_t* a, const uint32_t* b) {
    asm volatile("mma.sync.aligned.m16n8k8.row.col.f32.tf32.tf32.f32 "
        "{%0,%1,%2,%3}, {%4,%5,%6,%7}, {%8,%9}, {%0,%1,%2,%3};"
        : "+f"(c[0]), "+f"(c[1]), "+f"(c[2]), "+f"(c[3])
        : "r"(a[0]), "r"(a[1]), "r"(a[2]), "r"(a[3]), "r"(b[0]), "r"(b[1]));
}
__device__ __forceinline__ float tf32r(float x) {
    uint32_t o;
    asm("cvt.rna.tf32.f32 %0, %1;" : "=r"(o) : "f"(x));
    return __uint_as_float(o);
}

// FMA-pipe exp
__device__ __forceinline__ float fast_exp(float x) {
    x = fmaxf(x, -80.f);
    const float y = x * 1.4426950408889634f;
    const float fn = y + 12582912.f;
    const int ni = __float_as_int(fn) - 0x4B400000;
    const float f = y - (fn - 12582912.f);
    float p = 1.3333558146e-3f;
    p = fmaf(p, f, 9.6181291076e-3f);
    p = fmaf(p, f, 5.5504108664e-2f);
    p = fmaf(p, f, 2.4022650696e-1f);
    p = fmaf(p, f, 6.9314718056e-1f);
    p = fmaf(p, f, 1.0f);
    return p * __int_as_float((ni + 127) << 23);
}

__device__ __forceinline__ void store_split2(__nv_bfloat16* dst2, size_t stride2,
                                             int m, int khalf, int col,
                                             float v0, float v1) {
    __nv_bfloat16 h0 = __float2bfloat16(v0), h1 = __float2bfloat16(v1);
    float l0 = v0 - __bfloat162float(h0), l1 = v1 - __bfloat162float(h1);
    *(__nv_bfloat162*)(dst2 + (size_t)m * stride2 + col) = __halves2bfloat162(h0, h1);
    *(__nv_bfloat162*)(dst2 + (size_t)m * stride2 + khalf + col) = __floats2bfloat162_rn(l0, l1);
}

// ---------------------------------------------------------------------------
// fp32 -> [hi | lo] bf16 split conversion (weights). Rows >= Nrows zeroed.
// ---------------------------------------------------------------------------
__global__ __launch_bounds__(256) void convert_split_kernel(
    const float* __restrict__ X, __nv_bfloat16* __restrict__ X2,
    int Nrows, int K, int Npad)
{
    const long long idx = (long long)blockIdx.x * 256 + threadIdx.x;
    const int kq = K >> 2;
    const long long total = (long long)Npad * kq;
    if (idx >= total) return;
    const int n = (int)(idx / kq);
    const int k = (int)(idx - (long long)n * kq) * 4;
    float4 v = make_float4(0.f, 0.f, 0.f, 0.f);
    if (n < Nrows) v = *(const float4*)(X + (size_t)n * K + k);
    __nv_bfloat16 hx = __float2bfloat16(v.x);
    __nv_bfloat16 hy = __float2bfloat16(v.y);
    __nv_bfloat16 hz = __float2bfloat16(v.z);
    __nv_bfloat16 hw = __float2bfloat16(v.w);
    float lx = v.x - __bfloat162float(hx);
    float ly = v.y - __bfloat162float(hy);
    float lz = v.z - __bfloat162float(hz);
    float lw = v.w - __bfloat162float(hw);
    __nv_bfloat16* row = X2 + (size_t)n * 2 * K;
    __nv_bfloat162* ph = (__nv_bfloat162*)(row + k);
    ph[0] = __halves2bfloat162(hx, hy);
    ph[1] = __halves2bfloat162(hz, hw);
    __nv_bfloat162* pl = (__nv_bfloat162*)(row + K + k);
    pl[0] = __floats2bfloat162_rn(lx, ly);
    pl[1] = __floats2bfloat162_rn(lz, lw);
}

// ---------------------------------------------------------------------------
// Split-bf16 GEMM, split-K=3 (slice = segment): partials -> g_ws.
// 128x256 CTA tile, BK=64, double-buffered cp.async.
// grid (M/128, Npad/256, 3)
// ---------------------------------------------------------------------------
#define KSTRIDE_B 144
#define ATILE_B  (128 * KSTRIDE_B)
#define BTILE_B  (256 * KSTRIDE_B)
#define GSMEM_TOTAL (2 * ATILE_B + 2 * BTILE_B)

__device__ __forceinline__ void fill_tiles_mma(
    uint32_t aT, uint32_t bT,
    const __nv_bfloat16* __restrict__ A2, const __nv_bfloat16* __restrict__ W2,
    int Kp, int m0, int n0, int ka, int kw, int tid)
{
    #pragma unroll
    for (int i = 0; i < 4; i++) {
        int q = tid + 256 * i;
        int r = q >> 3, c = q & 7;
        cp16(aT + r * KSTRIDE_B + c * 16, A2 + (size_t)(m0 + r) * Kp + ka + c * 8);
    }
    #pragma unroll
    for (int i = 0; i < 8; i++) {
        int q = tid + 256 * i;
        int r = q >> 3, c = q & 7;
        cp16(bT + r * KSTRIDE_B + c * 16, W2 + (size_t)(n0 + r) * Kp + kw + c * 8);
    }
}

__global__ __launch_bounds__(256) void mma_gemm_sk(
    const __nv_bfloat16* __restrict__ A2, const __nv_bfloat16* __restrict__ W2,
    float* __restrict__ ws, int K, int Npad)
{
    extern __shared__ char smem[];
    const uint32_t sbase = smem_u32(smem);
    const uint32_t tA[2] = { sbase,                sbase + ATILE_B };
    const uint32_t tB[2] = { sbase + 2 * ATILE_B,  sbase + 2 * ATILE_B + BTILE_B };

    const int tid  = threadIdx.x;
    const int wid  = tid >> 5;
    const int lane = tid & 31;
    const int wm   = wid >> 2;
    const int wn   = wid & 3;
    const int m0 = blockIdx.x * 128;
    const int n0 = blockIdx.y * 256;
    const int z  = blockIdx.z;           // segment: 0=hh, 1=hi*lo, 2=lo*hi
    const int Kp = 2 * K;
    const int NCseg = K >> 6;

    const int kaBase = (z == 2) ? K : 0;
    const int kwBase = (z == 1) ? K : 0;

    const uint32_t aOff = (uint32_t)((wm * 64 + (lane & 15)) * KSTRIDE_B + (lane >> 4) * 16);
    const uint32_t bOff = (uint32_t)((wn * 64 + (lane & 7) + ((lane >> 4) & 1) * 8) * KSTRIDE_B
                                     + ((lane >> 3) & 1) * 16);

    float acc[4][8][4];
    #pragma unroll
    for (int i = 0; i < 4; i++)
        #pragma unroll
        for (int j = 0; j < 8; j++)
            #pragma unroll
            for (int q = 0; q < 4; q++) acc[i][j][q] = 0.f;

    fill_tiles_mma(tA[0], tB[0], A2, W2, Kp, m0, n0, kaBase, kwBase, tid);
    cp_commit();

    for (int c = 0; c < NCseg; c++) {
        const int b = c & 1;
        if (c + 1 < NCseg) {
            const int nb = (c + 1) & 1;
            const int kk = (c + 1) << 6;
            fill_tiles_mma(tA[nb], tB[nb], A2, W2, Kp, m0, n0,
                           kaBase + kk, kwBase + kk, tid);
            cp_commit();
            cp_wait1();
        } else {
            cp_wait0();
        }
        __syncthreads();

        #pragma unroll
        for (int ks = 0; ks < 4; ks++) {
            const uint32_t kb = (uint32_t)(ks * 32);
            uint32_t a[4][4];
            #pragma unroll
            for (int mf = 0; mf < 4; mf++)
                ldmatrix_x4(a[mf][0], a[mf][1], a[mf][2], a[mf][3],
                            tA[b] + aOff + mf * 16 * KSTRIDE_B + kb);
            uint32_t bb[8][2];
            #pragma unroll
            for (int bf = 0; bf < 4; bf++) {
                uint32_t r0, r1, r2, r3;
                ldmatrix_x4(r0, r1, r2, r3,
                            tB[b] + bOff + bf * 16 * KSTRIDE_B + kb);
                bb[bf * 2 + 0][0] = r0; bb[bf * 2 + 0][1] = r1;
                bb[bf * 2 + 1][0] = r2; bb[bf * 2 + 1][1] = r3;
            }
            #pragma unroll
            for (int mf = 0; mf < 4; mf++)
                #pragma unroll
                for (int nf = 0; nf < 8; nf++)
                    mma_bf16(acc[mf][nf][0], acc[mf][nf][1],
                             acc[mf][nf][2], acc[mf][nf][3],
                             a[mf][0], a[mf][1], a[mf][2], a[mf][3],
                             bb[nf][0], bb[nf][1]);
        }
        __syncthreads();
    }

    // write partials to padded workspace (no bounds checks needed)
    float* wz = ws + (size_t)z * T_TOK * Npad;
    const int g = lane >> 2;
    const int t = lane & 3;
    #pragma unroll
    for (int nf = 0; nf < 8; nf++) {
        const int col = n0 + wn * 64 + nf * 8 + t * 2;
        #pragma unroll
        for (int mf = 0; mf < 4; mf++) {
            const int r0 = m0 + wm * 64 + mf * 16 + g;
            *(float2*)(wz + (size_t)r0 * Npad + col) =
                make_float2(acc[mf][nf][0], acc[mf][nf][1]);
            *(float2*)(wz + (size_t)(r0 + 8) * Npad + col) =
                make_float2(acc[mf][nf][2], acc[mf][nf][3]);
        }
    }
}

// ---------------------------------------------------------------------------
// Reduce 3 slices + bias (+res) -> C (deterministic fixed order)
// ---------------------------------------------------------------------------
template<bool RES>
__global__ __launch_bounds__(256) void reduce3_kernel(
    const float* __restrict__ ws, const float* __restrict__ bias,
    const float* __restrict__ res, float* __restrict__ C,
    int Npad, int Nout)
{
    const int idx = blockIdx.x * 256 + threadIdx.x;
    const int q = Nout >> 2;
    if (idx >= T_TOK * q) return;
    const int m = idx / q;
    const int col = (idx - m * q) * 4;
    const size_t SL = (size_t)T_TOK * Npad;
    const float* p = ws + (size_t)m * Npad + col;
    const float4 a = *(const float4*)p;
    const float4 b = *(const float4*)(p + SL);
    const float4 c = *(const float4*)(p + 2 * SL);
    const float4 bb = *(const float4*)(bias + col);
    float4 v;
    v.x = a.x + b.x + c.x + bb.x;
    v.y = a.y + b.y + c.y + bb.y;
    v.z = a.z + b.z + c.z + bb.z;
    v.w = a.w + b.w + c.w + bb.w;
    if (RES) {
        const float4 r = *(const float4*)(res + (size_t)m * Nout + col);
        v.x += r.x; v.y += r.y; v.z += r.z; v.w += r.w;
    }
    *(float4*)(C + (size_t)m * Nout + col) = v;
}

// ---------------------------------------------------------------------------
// RMSNorm -> split-bf16 (fused)
// ---------------------------------------------------------------------------
__global__ __launch_bounds__(256) void rmsnorm_split_kernel(
    const float* __restrict__ x, const float* __restrict__ scale,
    __nv_bfloat16* __restrict__ a2)
{
    const int row = blockIdx.x;
    const float* xr = x + (size_t)row * HID;
    float s = 0.f;
    for (int i = threadIdx.x; i < HID; i += 256) { float v = xr[i]; s += v * v; }
    __shared__ float red[256];
    red[threadIdx.x] = s;
    __syncthreads();
    for (int off = 128; off > 0; off >>= 1) {
        if (threadIdx.x < off) red[threadIdx.x] += red[threadIdx.x + off];
        __syncthreads();
    }
    const float inv = rsqrtf(red[0] / (float)HID + EPSF);
    __nv_bfloat16* rowp = a2 + (size_t)row * 2 * HID;
    for (int i = threadIdx.x * 2; i < HID; i += 512) {
        float v0 = xr[i] * inv * scale[i];
        float v1 = xr[i + 1] * inv * scale[i + 1];
        __nv_bfloat16 h0 = __float2bfloat16(v0), h1 = __float2bfloat16(v1);
        *(__nv_bfloat162*)(rowp + i) = __halves2bfloat162(h0, h1);
        *(__nv_bfloat162*)(rowp + HID + i) = __floats2bfloat162_rn(
            v0 - __bfloat162float(h0), v1 - __bfloat162float(h1));
    }
}

// ---------------------------------------------------------------------------
// RoPE
// ---------------------------------------------------------------------------
__global__ void rope_kernel(float* __restrict__ qkv)
{
    const int t = blockIdx.x;
    const int head = blockIdx.y;
    const int i = threadIdx.x;

    float* base;
    if (head < NH) base = qkv + (size_t)t * QKV_DIM + head * HD;
    else           base = qkv + (size_t)t * QKV_DIM + NH * HD + (head - NH) * HD;

    const float PI = 3.14159265358979323846f;
    const float rope_base = 150000.f;
    const float freq = powf(rope_base, (float)i / 32.f);
    const float conc = 0.1f * logf(32.f) + 1.f;
    const float lg = logf(rope_base);
    const float low  = 32.f * logf(4096.f / (32.f * 2.f * PI)) / lg;
    const float high = 32.f * logf(4096.f / (2.f * PI)) / lg;
    const float interp = 1.f / (32.f * freq);
    const float extrap = 1.f / freq;
    float ramp = ((float)i - low) / (high - low);
    ramp = fminf(fmaxf(ramp, 0.f), 1.f);
    const float mask = 1.f - ramp;
    const float invf = interp * (1.f - mask) + extrap * mask;
    const float ang = (float)t * invf;
    const float c = cosf(ang) * conc;
    const float s = sinf(ang) * conc;

    const float x1 = base[i];
    const float x2 = base[i + 32];
    base[i]      = x1 * c - x2 * s;
    base[i + 32] = x2 * c + x1 * s;
}

// ---------------------------------------------------------------------------
// Causal GQA flash attention (tf32 mma + FMA-pipe exp), split-bf16 output
// ---------------------------------------------------------------------------
#define ATQ 68
#define ATV 72
#define ATTN_SMEM ((3 * 64 * ATQ + 64 * ATV + 3 * 64 + 2 * 256) * (int)sizeof(float))

__global__ __launch_bounds__(256) void attn_mma_kernel(
    const float* __restrict__ qkv, __nv_bfloat16* __restrict__ o2)
{
    extern __shared__ float sm[];
    float* Qs   = sm;
    float* Ks   = Qs + 64 * ATQ;
    float* Ss   = Ks + 64 * ATQ;
    float* Vs   = Ss + 64 * ATQ;
    float* mrow = Vs + 64 * ATV;
    float* lrow = mrow + 64;
    float* arow = lrow + 64;
    float* pm   = arow + 64;
    float* ps   = pm + 256;

    const int qt = blockIdx.x, h = blockIdx.y, kh = h >> 3;
    const int tid = threadIdx.x, wid = tid >> 5, lane = tid & 31;
    const int wm = wid >> 2, wn = wid & 3;
    const int g = lane >> 2, qd = lane & 3;
    const int sr = tid & 63, sq = tid >> 6;

    for (int i = tid; i < 64 * 64; i += 256) {
        int r = i >> 6, d = i & 63;
        Qs[r * ATQ + d] = tf32r(qkv[(size_t)(qt * 64 + r) * QKV_DIM + h * HD + d]);
    }
    if (tid < 64) { mrow[tid] = -1e30f; lrow[tid] = 0.f; }
    float o[2][2][4];
    #pragma unroll
    for (int i = 0; i < 2; i++)
        #pragma unroll
        for (int j = 0; j < 2; j++)
            #pragma unroll
            for (int q = 0; q < 4; q++) o[i][j][q] = 0.f;
    __syncthreads();

    for (int kt = 0; kt <= qt; kt++) {
        for (int i = tid; i < 64 * 64; i += 256) {
            int r = i >> 6, d = i & 63;
            size_t base = (size_t)(kt * 64 + r) * QKV_DIM;
            Ks[r * ATQ + d] = tf32r(qkv[base + NH * HD + kh * HD + d]);
            Vs[r * ATV + d] = tf32r(qkv[base + (NH + KVH) * HD + kh * HD + d]);
        }
        __syncthreads();

        float s[2][2][4];
        #pragma unroll
        for (int i = 0; i < 2; i++)
            #pragma unroll
            for (int j = 0; j < 2; j++)
                #pragma unroll
                for (int q = 0; q < 4; q++) s[i][j][q] = 0.f;
        #pragma unroll
        for (int k8 = 0; k8 < 8; k8++) {
            const int k0 = k8 * 8;
            uint32_t a[2][4], b[2][2];
            #pragma unroll
            for (int mf = 0; mf < 2; mf++) {
                const int rb = wm * 32 + mf * 16;
                a[mf][0] = __float_as_uint(Qs[(rb + g) * ATQ + k0 + qd]);
                a[mf][1] = __float_as_uint(Qs[(rb + g + 8) * ATQ + k0 + qd]);
                a[mf][2] = __float_as_uint(Qs[(rb + g) * ATQ + k0 + 4 + qd]);
                a[mf][3] = __float_as_uint(Qs[(rb + g + 8) * ATQ + k0 + 4 + qd]);
            }
            #pragma unroll
            for (int nf = 0; nf < 2; nf++) {
                const int nb = wn * 16 + nf * 8;
                b[nf][0] = __float_as_uint(Ks[(nb + g) * ATQ + k0 + qd]);
                b[nf][1] = __float_as_uint(Ks[(nb + g) * ATQ + k0 + 4 + qd]);
            }
            #pragma unroll
            for (int mf = 0; mf < 2; mf++)
                #pragma unroll
                for (int nf = 0; nf < 2; nf++)
                    mma_tf32(s[mf][nf], a[mf], b[nf]);
        }
        #pragma unroll
        for (int mf = 0; mf < 2; mf++)
            #pragma unroll
            for (int nf = 0; nf < 2; nf++) {
                const int r0 = wm * 32 + mf * 16 + g;
                const int c0 = wn * 16 + nf * 8 + 2 * qd;
                *(float2*)&Ss[r0 * ATQ + c0] =
                    make_float2(s[mf][nf][0] * SM_SCALE, s[mf][nf][1] * SM_SCALE);
                *(float2*)&Ss[(r0 + 8) * ATQ + c0] =
                    make_float2(s[mf][nf][2] * SM_SCALE, s[mf][nf][3] * SM_SCALE);
            }
        __syncthreads();

        {
            const int cmax = (kt == qt) ? (sr + 1) : 64;
            const int c0 = sq * 16;
            float mx = -1e30f;
            #pragma unroll
            for (int c = c0; c < c0 + 16; c++)
                if (c < cmax) mx = fmaxf(mx, Ss[sr * ATQ + c]);
            pm[sq * 64 + sr] = mx;
            __syncthreads();
            const float mold = mrow[sr];
            const float mfin = fmaxf(mold,
                fmaxf(fmaxf(pm[sr], pm[64 + sr]), fmaxf(pm[128 + sr], pm[192 + sr])));
            float sum = 0.f;
            #pragma unroll
            for (int c = c0; c < c0 + 16; c++) {
                float p = (c < cmax) ? fast_exp(Ss[sr * ATQ + c] - mfin) : 0.f;
                Ss[sr * ATQ + c] = tf32r(p);
                sum += p;
            }
            ps[sq * 64 + sr] = sum;
            __syncthreads();
            if (sq == 0) {
                const float alpha = fast_exp(mold - mfin);
                mrow[sr] = mfin;
                lrow[sr] = lrow[sr] * alpha
                         + ps[sr] + ps[64 + sr] + ps[128 + sr] + ps[192 + sr];
                arow[sr] = alpha;
            }
            __syncthreads();
        }

        #pragma unroll
        for (int mf = 0; mf < 2; mf++) {
            const int r0 = wm * 32 + mf * 16 + g;
            const float al0 = arow[r0], al1 = arow[r0 + 8];
            #pragma unroll
            for (int nf = 0; nf < 2; nf++) {
                o[mf][nf][0] *= al0; o[mf][nf][1] *= al0;
                o[mf][nf][2] *= al1; o[mf][nf][3] *= al1;
            }
        }
        #pragma unroll
        for (int k8 = 0; k8 < 8; k8++) {
            const int k0 = k8 * 8;
            uint32_t a[2][4], b[2][2];
            #pragma unroll
            for (int mf = 0; mf < 2; mf++) {
                const int rb = wm * 32 + mf * 16;
                a[mf][0] = __float_as_uint(Ss[(rb + g) * ATQ + k0 + qd]);
                a[mf][1] = __float_as_uint(Ss[(rb + g + 8) * ATQ + k0 + qd]);
                a[mf][2] = __float_as_uint(Ss[(rb + g) * ATQ + k0 + 4 + qd]);
                a[mf][3] = __float_as_uint(Ss[(rb + g + 8) * ATQ + k0 + 4 + qd]);
            }
            #pragma unroll
            for (int nf = 0; nf < 2; nf++) {
                const int nb = wn * 16 + nf * 8;
                b[nf][0] = __float_as_uint(Vs[(k0 + qd) * ATV + nb + g]);
                b[nf][1] = __float_as_uint(Vs[(k0 + 4 + qd) * ATV + nb + g]);
            }
            #pragma unroll
            for (int mf = 0; mf < 2; mf++)
                #pragma unroll
                for (int nf = 0; nf < 2; nf++)
                    mma_tf32(o[mf][nf], a[mf], b[nf]);
        }
        __syncthreads();
    }

    #pragma unroll
    for (int mf = 0; mf < 2; mf++) {
        const int r0 = wm * 32 + mf * 16 + g;
        const float li0 = 1.f / lrow[r0];
        const float li1 = 1.f / lrow[r0 + 8];
        #pragma unroll
        for (int nf = 0; nf < 2; nf++) {
            const int col = h * HD + wn * 16 + nf * 8 + 2 * qd;
            store_split2(o2, 2 * O_DIM, qt * 64 + r0, O_DIM, col,
                         o[mf][nf][0] * li0, o[mf][nf][1] * li0);
            store_split2(o2, 2 * O_DIM, qt * 64 + r0 + 8, O_DIM, col,
                         o[mf][nf][2] * li1, o[mf][nf][3] * li1);
        }
    }
}

// ---------------------------------------------------------------------------
// Clamped SwiGLU -> split-bf16 (fused)
// ---------------------------------------------------------------------------
__global__ __launch_bounds__(256) void act_split_kernel(
    const float* __restrict__ u, __nv_bfloat16* __restrict__ a2)
{
    const int idx = blockIdx.x * 256 + threadIdx.x;
    if (idx >= T_TOK * INTER) return;
    const int row = idx / INTER, col = idx - row * INTER;
    float gx  = u[(size_t)row * U_DIM + 2 * col];
    float lin = u[(size_t)row * U_DIM + 2 * col + 1];
    gx  = fminf(gx, 7.f);
    lin = fminf(fmaxf(lin, -7.f), 7.f);
    const float sg = 1.f / (1.f + fast_exp(-1.702f * gx));
    const float v = gx * sg * (lin + 1.f);
    __nv_bfloat16 hi = __float2bfloat16(v);
    a2[(size_t)row * 2 * INTER + col] = hi;
    a2[(size_t)row * 2 * INTER + INTER + col] =
        __float2bfloat16(v - __bfloat162float(hi));
}

// ---------------------------------------------------------------------------
// Launch
// ---------------------------------------------------------------------------
static inline int cdiv_ll(long long a, int b) { return (int)((a + b - 1) / b); }

extern "C" void kernel_launch(void* const* d_in, const int* in_sizes, int n_in,
                              void* d_out, int out_size)
{
    const float* x        = (const float*)d_in[0];
    const float* an_scale = (const float*)d_in[1];
    const float* wqkv     = (const float*)d_in[2];
    const float* bqkv     = (const float*)d_in[3];
    const float* wout     = (const float*)d_in[4];
    const float* bout     = (const float*)d_in[5];
    const float* mn_scale = (const float*)d_in[6];
    const float* w1       = (const float*)d_in[7];
    const float* b1       = (const float*)d_in[8];
    const float* w2       = (const float*)d_in[9];
    const float* b2       = (const float*)d_in[10];
    float* out = (float*)d_out;

    static float *qkv_p = nullptr, *h_p, *u_p, *ws_p;
    static __nv_bfloat16 *w2qkv_p, *w2out_p, *w2up_p, *w2dn_p, *a2_p;
    if (!qkv_p) {
        cudaGetSymbolAddress((void**)&qkv_p,  g_qkv);
        cudaGetSymbolAddress((void**)&h_p,    g_h);
        cudaGetSymbolAddress((void**)&u_p,    g_u);
        cudaGetSymbolAddress((void**)&ws_p,   g_ws);
        cudaGetSymbolAddress((void**)&w2qkv_p, g_w2_qkv);
        cudaGetSymbolAddress((void**)&w2out_p, g_w2_out);
        cudaGetSymbolAddress((void**)&w2up_p,  g_w2_up);
        cudaGetSymbolAddress((void**)&w2dn_p,  g_w2_dn);
        cudaGetSymbolAddress((void**)&a2_p,    g_a2);
    }
    cudaFuncSetAttribute(attn_mma_kernel,
                         cudaFuncAttributeMaxDynamicSharedMemorySize, ATTN_SMEM);
    cudaFuncSetAttribute(mma_gemm_sk,
                         cudaFuncAttributeMaxDynamicSharedMemorySize, GSMEM_TOTAL);

    // Weight splits
    convert_split_kernel<<<cdiv_ll((long long)QKV_DIM * HID / 4, 256), 256>>>(
        wqkv, w2qkv_p, QKV_DIM, HID, QKV_DIM);
    convert_split_kernel<<<cdiv_ll((long long)NPAD_OUT * O_DIM / 4, 256), 256>>>(
        wout, w2out_p, HID, O_DIM, NPAD_OUT);
    convert_split_kernel<<<cdiv_ll((long long)NPAD_UP * HID / 4, 256), 256>>>(
        w1, w2up_p, U_DIM, HID, NPAD_UP);
    convert_split_kernel<<<cdiv_ll((long long)NPAD_DN * INTER / 4, 256), 256>>>(
        w2, w2dn_p, HID, INTER, NPAD_DN);

    // 1) attn rmsnorm -> split a2
    rmsnorm_split_kernel<<<T_TOK, 256>>>(x, an_scale, a2_p);

    // 2) QKV GEMM (split-K=3) + reduce
    {
        dim3 grid(T_TOK / 128, QKV_DIM / 256, 3);
        mma_gemm_sk<<<grid, 256, GSMEM_TOTAL>>>(a2_p, w2qkv_p, ws_p, HID, QKV_DIM);
        reduce3_kernel<false><<<cdiv_ll((long long)T_TOK * QKV_DIM / 4, 256), 256>>>(
            ws_p, bqkv, nullptr, qkv_p, QKV_DIM, QKV_DIM);
    }

    // 3) RoPE
    {
        dim3 grid(T_TOK, NH + KVH);
        rope_kernel<<<grid, 32>>>(qkv_p);
    }

    // 4) attention (writes split a2, K=4096)
    {
        dim3 grid(T_TOK / 64, NH);
        attn_mma_kernel<<<grid, 256, ATTN_SMEM>>>(qkv_p, a2_p);
    }

    // 5) out GEMM + residual
    {
        dim3 grid(T_TOK / 128, NPAD_OUT / 256, 3);
        mma_gemm_sk<<<grid, 256, GSMEM_TOTAL>>>(a2_p, w2out_p, ws_p, O_DIM, NPAD_OUT);
        reduce3_kernel<true><<<cdiv_ll((long long)T_TOK * HID / 4, 256), 256>>>(
            ws_p, bout, x, h_p, NPAD_OUT, HID);
    }

    // 6) mlp rmsnorm -> split a2
    rmsnorm_split_kernel<<<T_TOK, 256>>>(h_p, mn_scale, a2_p);

    // 7) MLP up GEMM
    {
        dim3 grid(T_TOK / 128, NPAD_UP / 256, 3);
        mma_gemm_sk<<<grid, 256, GSMEM_TOTAL>>>(a2_p, w2up_p, ws_p, HID, NPAD_UP);
        reduce3_kernel<false><<<cdiv_ll((long long)T_TOK * U_DIM / 4, 256), 256>>>(
            ws_p, b1, nullptr, u_p, NPAD_UP, U_DIM);
    }

    // 8) activation -> split a2
    act_split_kernel<<<(T_TOK * INTER + 255) / 256, 256>>>(u_p, a2_p);

    // 9) MLP down GEMM + residual -> out
    {
        dim3 grid(T_TOK / 128, NPAD_DN / 256, 3);
        mma_gemm_sk<<<grid, 256, GSMEM_TOTAL>>>(a2_p, w2dn_p, ws_p, INTER, NPAD_DN);
        reduce3_kernel<true><<<cdiv_ll((long long)T_TOK * HID / 4, 256), 256>>>(
            ws_p, b2, h_p, out, NPAD_DN, HID);
    }
}

// round 9
// speedup vs baseline: 1.5194x; 1.0334x over previous
#include <cuda_runtime.h>
#include <cuda_bf16.h>
#include <math.h>
#include <stdint.h>

// ---------------------------------------------------------------------------
// Problem constants
// ---------------------------------------------------------------------------
#define T_TOK   1024
#define HID     2880
#define NH      64
#define KVH     8
#define HD      64
#define INTER   2880
#define QKV_DIM (HD*(NH+2*KVH))      // 5120
#define O_DIM   (NH*HD)              // 4096
#define U_DIM   (2*INTER)            // 5760
#define SM_SCALE 0.125f
#define EPSF    1e-5f

#define NPAD_OUT 3072
#define NPAD_UP  5888
#define NPAD_DN  3072

// ---------------------------------------------------------------------------
// Scratch
// ---------------------------------------------------------------------------
__device__ float g_qkv[T_TOK * QKV_DIM];
__device__ float g_h  [T_TOK * HID];
__device__ float g_ws [6 * T_TOK * QKV_DIM];     // split-K partials (max: 6 slices qkv)
__device__ float g_rope[T_TOK * 64];             // per-token cos[0:32], sin[32:64]

__device__ __align__(256) __nv_bfloat16 g_w2_qkv[QKV_DIM * 2 * HID];
__device__ __align__(256) __nv_bfloat16 g_w2_out[NPAD_OUT * 2 * O_DIM];
__device__ __align__(256) __nv_bfloat16 g_w2_up [NPAD_UP  * 2 * HID];
__device__ __align__(256) __nv_bfloat16 g_w2_dn [NPAD_DN  * 2 * INTER];
__device__ __align__(256) __nv_bfloat16 g_a2    [T_TOK * 2 * O_DIM];

// ---------------------------------------------------------------------------
// PTX helpers
// ---------------------------------------------------------------------------
__device__ __forceinline__ uint32_t smem_u32(const void* p) {
    uint32_t a;
    asm("{ .reg .u64 t; cvta.to.shared.u64 t, %1; cvt.u32.u64 %0, t; }" : "=r"(a) : "l"(p));
    return a;
}
__device__ __forceinline__ void cp16(uint32_t dst, const void* src) {
    asm volatile("cp.async.cg.shared.global [%0], [%1], 16;" :: "r"(dst), "l"(src));
}
__device__ __forceinline__ void cp_commit() {
    asm volatile("cp.async.commit_group;" ::: "memory");
}
__device__ __forceinline__ void cp_wait1() {
    asm volatile("cp.async.wait_group 1;" ::: "memory");
}
__device__ __forceinline__ void cp_wait0() {
    asm volatile("cp.async.wait_group 0;" ::: "memory");
}
__device__ __forceinline__ void ldmatrix_x4(uint32_t& r0, uint32_t& r1,
                                            uint32_t& r2, uint32_t& r3, uint32_t addr) {
    asm volatile("ldmatrix.sync.aligned.m8n8.x4.shared.b16 {%0,%1,%2,%3}, [%4];"
        : "=r"(r0), "=r"(r1), "=r"(r2), "=r"(r3) : "r"(addr));
}
__device__ __forceinline__ void mma_bf16(float& c0, float& c1, float& c2, float& c3,
                                         uint32_t a0, uint32_t a1, uint32_t a2, uint32_t a3,
                                         uint32_t b0, uint32_t b1) {
    asm volatile("mma.sync.aligned.m16n8k16.row.col.f32.bf16.bf16.f32 "
        "{%0,%1,%2,%3}, {%4,%5,%6,%7}, {%8,%9}, {%0,%1,%2,%3};"
        : "+f"(c0), "+f"(c1), "+f"(c2), "+f"(c3)
        : "r"(a0), "r"(a1), "r"(a2), "r"(a3), "r"(b0), "r"(b1));
}
__device__ __forceinline__ void mma_tf32(float* c, const uint32_t* a, const uint32_t* b) {
    asm volatile("mma.sync.aligned.m16n8k8.row.col.f32.tf32.tf32.f32 "
        "{%0,%1,%2,%3}, {%4,%5,%6,%7}, {%8,%9}, {%0,%1,%2,%3};"
        : "+f"(c[0]), "+f"(c[1]), "+f"(c[2]), "+f"(c[3])
        : "r"(a[0]), "r"(a[1]), "r"(a[2]), "r"(a[3]), "r"(b[0]), "r"(b[1]));
}
__device__ __forceinline__ float tf32r(float x) {
    uint32_t o;
    asm("cvt.rna.tf32.f32 %0, %1;" : "=r"(o) : "f"(x));
    return __uint_as_float(o);
}

// FMA-pipe exp
__device__ __forceinline__ float fast_exp(float x) {
    x = fmaxf(x, -80.f);
    const float y = x * 1.4426950408889634f;
    const float fn = y + 12582912.f;
    const int ni = __float_as_int(fn) - 0x4B400000;
    const float f = y - (fn - 12582912.f);
    float p = 1.3333558146e-3f;
    p = fmaf(p, f, 9.6181291076e-3f);
    p = fmaf(p, f, 5.5504108664e-2f);
    p = fmaf(p, f, 2.4022650696e-1f);
    p = fmaf(p, f, 6.9314718056e-1f);
    p = fmaf(p, f, 1.0f);
    return p * __int_as_float((ni + 127) << 23);
}

__device__ __forceinline__ void store_split2(__nv_bfloat16* dst2, size_t stride2,
                                             int m, int khalf, int col,
                                             float v0, float v1) {
    __nv_bfloat16 h0 = __float2bfloat16(v0), h1 = __float2bfloat16(v1);
    float l0 = v0 - __bfloat162float(h0), l1 = v1 - __bfloat162float(h1);
    *(__nv_bfloat162*)(dst2 + (size_t)m * stride2 + col) = __halves2bfloat162(h0, h1);
    *(__nv_bfloat162*)(dst2 + (size_t)m * stride2 + khalf + col) = __floats2bfloat162_rn(l0, l1);
}

// ---------------------------------------------------------------------------
// fp32 -> [hi | lo] bf16 split conversion (weights). 2D grid, div-free.
// grid ((K/4 + 255)/256, Npad), block 256, 4 elems/thread. (proven r7 body)
// ---------------------------------------------------------------------------
__global__ __launch_bounds__(256) void convert_split_kernel(
    const float* __restrict__ X, __nv_bfloat16* __restrict__ X2,
    int Nrows, int K)
{
    const int n = blockIdx.y;
    const int k = (blockIdx.x * 256 + threadIdx.x) * 4;
    if (k >= K) return;
    float4 v = make_float4(0.f, 0.f, 0.f, 0.f);
    if (n < Nrows) v = *(const float4*)(X + (size_t)n * K + k);
    __nv_bfloat16 hx = __float2bfloat16(v.x);
    __nv_bfloat16 hy = __float2bfloat16(v.y);
    __nv_bfloat16 hz = __float2bfloat16(v.z);
    __nv_bfloat16 hw = __float2bfloat16(v.w);
    float lx = v.x - __bfloat162float(hx);
    float ly = v.y - __bfloat162float(hy);
    float lz = v.z - __bfloat162float(hz);
    float lw = v.w - __bfloat162float(hw);
    __nv_bfloat16* row = X2 + (size_t)n * 2 * K;
    __nv_bfloat162* ph = (__nv_bfloat162*)(row + k);
    ph[0] = __halves2bfloat162(hx, hy);
    ph[1] = __halves2bfloat162(hz, hw);
    __nv_bfloat162* pl = (__nv_bfloat162*)(row + K + k);
    pl[0] = __floats2bfloat162_rn(lx, ly);
    pl[1] = __floats2bfloat162_rn(lz, lw);
}

// ---------------------------------------------------------------------------
// Split-bf16 GEMM, split-K (3 segments x S sub-slices): partials -> ws.
// grid (M/128, Npad/256, 3*S)
// ---------------------------------------------------------------------------
#define KSTRIDE_B 144
#define ATILE_B  (128 * KSTRIDE_B)
#define BTILE_B  (256 * KSTRIDE_B)
#define GSMEM_TOTAL (2 * ATILE_B + 2 * BTILE_B)

__device__ __forceinline__ void fill_tiles_mma(
    uint32_t aT, uint32_t bT,
    const __nv_bfloat16* __restrict__ A2, const __nv_bfloat16* __restrict__ W2,
    int Kp, int m0, int n0, int ka, int kw, int tid)
{
    #pragma unroll
    for (int i = 0; i < 4; i++) {
        int q = tid + 256 * i;
        int r = q >> 3, c = q & 7;
        cp16(aT + r * KSTRIDE_B + c * 16, A2 + (size_t)(m0 + r) * Kp + ka + c * 8);
    }
    #pragma unroll
    for (int i = 0; i < 8; i++) {
        int q = tid + 256 * i;
        int r = q >> 3, c = q & 7;
        cp16(bT + r * KSTRIDE_B + c * 16, W2 + (size_t)(n0 + r) * Kp + kw + c * 8);
    }
}

__global__ __launch_bounds__(256) void mma_gemm_sk(
    const __nv_bfloat16* __restrict__ A2, const __nv_bfloat16* __restrict__ W2,
    float* __restrict__ ws, int K, int Npad, int S)
{
    extern __shared__ char smem[];
    const uint32_t sbase = smem_u32(smem);
    const uint32_t tA[2] = { sbase,                sbase + ATILE_B };
    const uint32_t tB[2] = { sbase + 2 * ATILE_B,  sbase + 2 * ATILE_B + BTILE_B };

    const int tid  = threadIdx.x;
    const int wid  = tid >> 5;
    const int lane = tid & 31;
    const int wm   = wid >> 2;
    const int wn   = wid & 3;
    const int m0 = blockIdx.x * 128;
    const int n0 = blockIdx.y * 256;
    const int z  = blockIdx.z;
    const int seg = z / S;               // 0=hh, 1=hi*lo, 2=lo*hi
    const int sub = z - seg * S;
    const int Kp = 2 * K;
    const int NCseg = K >> 6;
    const int cb = (sub * NCseg) / S;
    const int ce = ((sub + 1) * NCseg) / S;

    const int kaBase = (seg == 2) ? K : 0;
    const int kwBase = (seg == 1) ? K : 0;

    const uint32_t aOff = (uint32_t)((wm * 64 + (lane & 15)) * KSTRIDE_B + (lane >> 4) * 16);
    const uint32_t bOff = (uint32_t)((wn * 64 + (lane & 7) + ((lane >> 4) & 1) * 8) * KSTRIDE_B
                                     + ((lane >> 3) & 1) * 16);

    float acc[4][8][4];
    #pragma unroll
    for (int i = 0; i < 4; i++)
        #pragma unroll
        for (int j = 0; j < 8; j++)
            #pragma unroll
            for (int q = 0; q < 4; q++) acc[i][j][q] = 0.f;

    fill_tiles_mma(tA[0], tB[0], A2, W2, Kp, m0, n0,
                   kaBase + (cb << 6), kwBase + (cb << 6), tid);
    cp_commit();

    for (int c = cb; c < ce; c++) {
        const int b = (c - cb) & 1;
        if (c + 1 < ce) {
            const int nb = (c + 1 - cb) & 1;
            const int kk = (c + 1) << 6;
            fill_tiles_mma(tA[nb], tB[nb], A2, W2, Kp, m0, n0,
                           kaBase + kk, kwBase + kk, tid);
            cp_commit();
            cp_wait1();
        } else {
            cp_wait0();
        }
        __syncthreads();

        #pragma unroll
        for (int ks = 0; ks < 4; ks++) {
            const uint32_t kb = (uint32_t)(ks * 32);
            uint32_t a[4][4];
            #pragma unroll
            for (int mf = 0; mf < 4; mf++)
                ldmatrix_x4(a[mf][0], a[mf][1], a[mf][2], a[mf][3],
                            tA[b] + aOff + mf * 16 * KSTRIDE_B + kb);
            uint32_t bb[8][2];
            #pragma unroll
            for (int bf = 0; bf < 4; bf++) {
                uint32_t r0, r1, r2, r3;
                ldmatrix_x4(r0, r1, r2, r3,
                            tB[b] + bOff + bf * 16 * KSTRIDE_B + kb);
                bb[bf * 2 + 0][0] = r0; bb[bf * 2 + 0][1] = r1;
                bb[bf * 2 + 1][0] = r2; bb[bf * 2 + 1][1] = r3;
            }
            #pragma unroll
            for (int mf = 0; mf < 4; mf++)
                #pragma unroll
                for (int nf = 0; nf < 8; nf++)
                    mma_bf16(acc[mf][nf][0], acc[mf][nf][1],
                             acc[mf][nf][2], acc[mf][nf][3],
                             a[mf][0], a[mf][1], a[mf][2], a[mf][3],
                             bb[nf][0], bb[nf][1]);
        }
        __syncthreads();
    }

    float* wz = ws + (size_t)z * T_TOK * Npad;
    const int g = lane >> 2;
    const int t = lane & 3;
    #pragma unroll
    for (int nf = 0; nf < 8; nf++) {
        const int col = n0 + wn * 64 + nf * 8 + t * 2;
        #pragma unroll
        for (int mf = 0; mf < 4; mf++) {
            const int r0 = m0 + wm * 64 + mf * 16 + g;
            *(float2*)(wz + (size_t)r0 * Npad + col) =
                make_float2(acc[mf][nf][0], acc[mf][nf][1]);
            *(float2*)(wz + (size_t)(r0 + 8) * Npad + col) =
                make_float2(acc[mf][nf][2], acc[mf][nf][3]);
        }
    }
}

// ---------------------------------------------------------------------------
// Rope table: cos/sin per (t, d)
// ---------------------------------------------------------------------------
__global__ void rope_table_kernel(float* __restrict__ tab)
{
    const int t = blockIdx.x;
    const int i = threadIdx.x;   // 0..31
    const float PI = 3.14159265358979323846f;
    const float rope_base = 150000.f;
    const float freq = powf(rope_base, (float)i / 32.f);
    const float conc = 0.1f * logf(32.f) + 1.f;
    const float lg = logf(rope_base);
    const float low  = 32.f * logf(4096.f / (32.f * 2.f * PI)) / lg;
    const float high = 32.f * logf(4096.f / (2.f * PI)) / lg;
    const float interp = 1.f / (32.f * freq);
    const float extrap = 1.f / freq;
    float ramp = ((float)i - low) / (high - low);
    ramp = fminf(fmaxf(ramp, 0.f), 1.f);
    const float mask = 1.f - ramp;
    const float invf = interp * (1.f - mask) + extrap * mask;
    const float ang = (float)t * invf;
    tab[t * 64 + i]      = cosf(ang) * conc;
    tab[t * 64 + 32 + i] = sinf(ang) * conc;
}

// ---------------------------------------------------------------------------
// QKV reduce (6 slices) + bias + RoPE -> qkv. grid (T_TOK), 256 thr.
// ---------------------------------------------------------------------------
__global__ __launch_bounds__(256) void reduce_qkv_rope_kernel(
    const float* __restrict__ ws, const float* __restrict__ bias,
    const float* __restrict__ tab, float* __restrict__ qkv)
{
    const int t = blockIdx.x;
    const int tid = threadIdx.x;
    const size_t SL = (size_t)T_TOK * QKV_DIM;
    const float* base = ws + (size_t)t * QKV_DIM;
    float* outr = qkv + (size_t)t * QKV_DIM;
    const float* tr = tab + t * 64;

    for (int p = tid; p < 72 * 32; p += 256) {
        const int head = p >> 5, d = p & 31;
        const int c1 = head * 64 + d, c2 = c1 + 32;
        float s1 = bias[c1], s2 = bias[c2];
        #pragma unroll
        for (int z = 0; z < 6; z++) {
            s1 += base[z * SL + c1];
            s2 += base[z * SL + c2];
        }
        const float cc = tr[d], ss = tr[32 + d];
        outr[c1] = s1 * cc - s2 * ss;
        outr[c2] = s2 * cc + s1 * ss;
    }
    for (int c = 4608 + tid; c < QKV_DIM; c += 256) {
        float s = bias[c];
        #pragma unroll
        for (int z = 0; z < 6; z++) s += base[z * SL + c];
        outr[c] = s;
    }
}

// ---------------------------------------------------------------------------
// out reduce (3) + bias + residual -> h, then rmsnorm -> split a2. grid (T_TOK).
// ---------------------------------------------------------------------------
__global__ __launch_bounds__(256) void reduce_out_rms_kernel(
    const float* __restrict__ ws, const float* __restrict__ bias,
    const float* __restrict__ res, const float* __restrict__ scale,
    float* __restrict__ h, __nv_bfloat16* __restrict__ a2)
{
    __shared__ float row[HID];
    __shared__ float red[256];
    const int t = blockIdx.x;
    const int tid = threadIdx.x;
    const size_t SL = (size_t)T_TOK * NPAD_OUT;
    const float* base = ws + (size_t)t * NPAD_OUT;
    const float* xr = res + (size_t)t * HID;
    float* hr = h + (size_t)t * HID;

    float sq = 0.f;
    for (int c = tid * 4; c < HID; c += 1024) {
        const float4 a = *(const float4*)(base + c);
        const float4 b = *(const float4*)(base + SL + c);
        const float4 d = *(const float4*)(base + 2 * SL + c);
        const float4 bb = *(const float4*)(bias + c);
        const float4 rv = *(const float4*)(xr + c);
        float4 v;
        v.x = a.x + b.x + d.x + bb.x + rv.x;
        v.y = a.y + b.y + d.y + bb.y + rv.y;
        v.z = a.z + b.z + d.z + bb.z + rv.z;
        v.w = a.w + b.w + d.w + bb.w + rv.w;
        *(float4*)(row + c) = v;
        *(float4*)(hr + c) = v;
        sq += v.x * v.x + v.y * v.y + v.z * v.z + v.w * v.w;
    }
    red[tid] = sq;
    __syncthreads();
    for (int off = 128; off > 0; off >>= 1) {
        if (tid < off) red[tid] += red[tid + off];
        __syncthreads();
    }
    const float inv = rsqrtf(red[0] / (float)HID + EPSF);
    __nv_bfloat16* rowp = a2 + (size_t)t * 2 * HID;
    for (int i = tid * 2; i < HID; i += 512) {
        float v0 = row[i] * inv * scale[i];
        float v1 = row[i + 1] * inv * scale[i + 1];
        __nv_bfloat16 h0 = __float2bfloat16(v0), h1 = __float2bfloat16(v1);
        *(__nv_bfloat162*)(rowp + i) = __halves2bfloat162(h0, h1);
        *(__nv_bfloat162*)(rowp + HID + i) = __floats2bfloat162_rn(
            v0 - __bfloat162float(h0), v1 - __bfloat162float(h1));
    }
}

// ---------------------------------------------------------------------------
// up reduce (3) + bias + clamped SwiGLU -> split a2. grid (6, T_TOK).
// ---------------------------------------------------------------------------
__global__ __launch_bounds__(256) void reduce_up_act_kernel(
    const float* __restrict__ ws, const float* __restrict__ bias,
    __nv_bfloat16* __restrict__ a2)
{
    const int t = blockIdx.y;
    const int j = blockIdx.x * 256 + threadIdx.x;   // 0..1439
    if (j >= INTER / 2) return;
    const int c = j * 4;
    const size_t SL = (size_t)T_TOK * NPAD_UP;
    const float* base = ws + (size_t)t * NPAD_UP + c;
    const float4 a = *(const float4*)base;
    const float4 b = *(const float4*)(base + SL);
    const float4 d = *(const float4*)(base + 2 * SL);
    const float4 bb = *(const float4*)(bias + c);
    float u0 = a.x + b.x + d.x + bb.x;
    float u1 = a.y + b.y + d.y + bb.y;
    float u2 = a.z + b.z + d.z + bb.z;
    float u3 = a.w + b.w + d.w + bb.w;

    float g0 = fminf(u0, 7.f), l0 = fminf(fmaxf(u1, -7.f), 7.f);
    float g1 = fminf(u2, 7.f), l1 = fminf(fmaxf(u3, -7.f), 7.f);
    const float v0 = g0 / (1.f + fast_exp(-1.702f * g0)) * (l0 + 1.f);
    const float v1 = g1 / (1.f + fast_exp(-1.702f * g1)) * (l1 + 1.f);

    __nv_bfloat16 h0 = __float2bfloat16(v0), h1 = __float2bfloat16(v1);
    __nv_bfloat16* rowp = a2 + (size_t)t * 2 * INTER;
    *(__nv_bfloat162*)(rowp + 2 * j) = __halves2bfloat162(h0, h1);
    *(__nv_bfloat162*)(rowp + INTER + 2 * j) = __floats2bfloat162_rn(
        v0 - __bfloat162float(h0), v1 - __bfloat162float(h1));
}

// ---------------------------------------------------------------------------
// dn reduce (3) + bias + residual -> out (final)
// ---------------------------------------------------------------------------
__global__ __launch_bounds__(256) void reduce_dn_kernel(
    const float* __restrict__ ws, const float* __restrict__ bias,
    const float* __restrict__ res, float* __restrict__ C)
{
    const int idx = blockIdx.x * 256 + threadIdx.x;
    const int q = HID >> 2;
    if (idx >= T_TOK * q) return;
    const int m = idx / q;
    const int col = (idx - m * q) * 4;
    const size_t SL = (size_t)T_TOK * NPAD_DN;
    const float* p = ws + (size_t)m * NPAD_DN + col;
    const float4 a = *(const float4*)p;
    const float4 b = *(const float4*)(p + SL);
    const float4 c = *(const float4*)(p + 2 * SL);
    const float4 bb = *(const float4*)(bias + col);
    const float4 r = *(const float4*)(res + (size_t)m * HID + col);
    float4 v;
    v.x = a.x + b.x + c.x + bb.x + r.x;
    v.y = a.y + b.y + c.y + bb.y + r.y;
    v.z = a.z + b.z + c.z + bb.z + r.z;
    v.w = a.w + b.w + c.w + bb.w + r.w;
    *(float4*)(C + (size_t)m * HID + col) = v;
}

// ---------------------------------------------------------------------------
// RMSNorm -> split-bf16 (first norm, on x)
// ---------------------------------------------------------------------------
__global__ __launch_bounds__(256) void rmsnorm_split_kernel(
    const float* __restrict__ x, const float* __restrict__ scale,
    __nv_bfloat16* __restrict__ a2)
{
    const int row = blockIdx.x;
    const float* xr = x + (size_t)row * HID;
    float s = 0.f;
    for (int i = threadIdx.x; i < HID; i += 256) { float v = xr[i]; s += v * v; }
    __shared__ float red[256];
    red[threadIdx.x] = s;
    __syncthreads();
    for (int off = 128; off > 0; off >>= 1) {
        if (threadIdx.x < off) red[threadIdx.x] += red[threadIdx.x + off];
        __syncthreads();
    }
    const float inv = rsqrtf(red[0] / (float)HID + EPSF);
    __nv_bfloat16* rowp = a2 + (size_t)row * 2 * HID;
    for (int i = threadIdx.x * 2; i < HID; i += 512) {
        float v0 = xr[i] * inv * scale[i];
        float v1 = xr[i + 1] * inv * scale[i + 1];
        __nv_bfloat16 h0 = __float2bfloat16(v0), h1 = __float2bfloat16(v1);
        *(__nv_bfloat162*)(rowp + i) = __halves2bfloat162(h0, h1);
        *(__nv_bfloat162*)(rowp + HID + i) = __floats2bfloat162_rn(
            v0 - __bfloat162float(h0), v1 - __bfloat162float(h1));
    }
}

// ---------------------------------------------------------------------------
// Causal GQA flash attention (tf32 mma + FMA-pipe exp), split-bf16 output
// ---------------------------------------------------------------------------
#define ATQ 68
#define ATV 72
#define ATTN_SMEM ((3 * 64 * ATQ + 64 * ATV + 3 * 64 + 2 * 256) * (int)sizeof(float))

__global__ __launch_bounds__(256) void attn_mma_kernel(
    const float* __restrict__ qkv, __nv_bfloat16* __restrict__ o2)
{
    extern __shared__ float sm[];
    float* Qs   = sm;
    float* Ks   = Qs + 64 * ATQ;
    float* Ss   = Ks + 64 * ATQ;
    float* Vs   = Ss + 64 * ATQ;
    float* mrow = Vs + 64 * ATV;
    float* lrow = mrow + 64;
    float* arow = lrow + 64;
    float* pm   = arow + 64;
    float* ps   = pm + 256;

    const int qt = blockIdx.x, h = blockIdx.y, kh = h >> 3;
    const int tid = threadIdx.x, wid = tid >> 5, lane = tid & 31;
    const int wm = wid >> 2, wn = wid & 3;
    const int g = lane >> 2, qd = lane & 3;
    const int sr = tid & 63, sq = tid >> 6;

    for (int i = tid; i < 64 * 64; i += 256) {
        int r = i >> 6, d = i & 63;
        Qs[r * ATQ + d] = tf32r(qkv[(size_t)(qt * 64 + r) * QKV_DIM + h * HD + d]);
    }
    if (tid < 64) { mrow[tid] = -1e30f; lrow[tid] = 0.f; }
    float o[2][2][4];
    #pragma unroll
    for (int i = 0; i < 2; i++)
        #pragma unroll
        for (int j = 0; j < 2; j++)
            #pragma unroll
            for (int q = 0; q < 4; q++) o[i][j][q] = 0.f;
    __syncthreads();

    for (int kt = 0; kt <= qt; kt++) {
        for (int i = tid; i < 64 * 64; i += 256) {
            int r = i >> 6, d = i & 63;
            size_t base = (size_t)(kt * 64 + r) * QKV_DIM;
            Ks[r * ATQ + d] = tf32r(qkv[base + NH * HD + kh * HD + d]);
            Vs[r * ATV + d] = tf32r(qkv[base + (NH + KVH) * HD + kh * HD + d]);
        }
        __syncthreads();

        float s[2][2][4];
        #pragma unroll
        for (int i = 0; i < 2; i++)
            #pragma unroll
            for (int j = 0; j < 2; j++)
                #pragma unroll
                for (int q = 0; q < 4; q++) s[i][j][q] = 0.f;
        #pragma unroll
        for (int k8 = 0; k8 < 8; k8++) {
            const int k0 = k8 * 8;
            uint32_t a[2][4], b[2][2];
            #pragma unroll
            for (int mf = 0; mf < 2; mf++) {
                const int rb = wm * 32 + mf * 16;
                a[mf][0] = __float_as_uint(Qs[(rb + g) * ATQ + k0 + qd]);
                a[mf][1] = __float_as_uint(Qs[(rb + g + 8) * ATQ + k0 + qd]);
                a[mf][2] = __float_as_uint(Qs[(rb + g) * ATQ + k0 + 4 + qd]);
                a[mf][3] = __float_as_uint(Qs[(rb + g + 8) * ATQ + k0 + 4 + qd]);
            }
            #pragma unroll
            for (int nf = 0; nf < 2; nf++) {
                const int nb = wn * 16 + nf * 8;
                b[nf][0] = __float_as_uint(Ks[(nb + g) * ATQ + k0 + qd]);
                b[nf][1] = __float_as_uint(Ks[(nb + g) * ATQ + k0 + 4 + qd]);
            }
            #pragma unroll
            for (int mf = 0; mf < 2; mf++)
                #pragma unroll
                for (int nf = 0; nf < 2; nf++)
                    mma_tf32(s[mf][nf], a[mf], b[nf]);
        }
        #pragma unroll
        for (int mf = 0; mf < 2; mf++)
            #pragma unroll
            for (int nf = 0; nf < 2; nf++) {
                const int r0 = wm * 32 + mf * 16 + g;
                const int c0 = wn * 16 + nf * 8 + 2 * qd;
                *(float2*)&Ss[r0 * ATQ + c0] =
                    make_float2(s[mf][nf][0] * SM_SCALE, s[mf][nf][1] * SM_SCALE);
                *(float2*)&Ss[(r0 + 8) * ATQ + c0] =
                    make_float2(s[mf][nf][2] * SM_SCALE, s[mf][nf][3] * SM_SCALE);
            }
        __syncthreads();

        {
            const int cmax = (kt == qt) ? (sr + 1) : 64;
            const int c0 = sq * 16;
            float mx = -1e30f;
            #pragma unroll
            for (int c = c0; c < c0 + 16; c++)
                if (c < cmax) mx = fmaxf(mx, Ss[sr * ATQ + c]);
            pm[sq * 64 + sr] = mx;
            __syncthreads();
            const float mold = mrow[sr];
            const float mfin = fmaxf(mold,
                fmaxf(fmaxf(pm[sr], pm[64 + sr]), fmaxf(pm[128 + sr], pm[192 + sr])));
            float sum = 0.f;
            #pragma unroll
            for (int c = c0; c < c0 + 16; c++) {
                float p = (c < cmax) ? fast_exp(Ss[sr * ATQ + c] - mfin) : 0.f;
                Ss[sr * ATQ + c] = tf32r(p);
                sum += p;
            }
            ps[sq * 64 + sr] = sum;
            __syncthreads();
            if (sq == 0) {
                const float alpha = fast_exp(mold - mfin);
                mrow[sr] = mfin;
                lrow[sr] = lrow[sr] * alpha
                         + ps[sr] + ps[64 + sr] + ps[128 + sr] + ps[192 + sr];
                arow[sr] = alpha;
            }
            __syncthreads();
        }

        #pragma unroll
        for (int mf = 0; mf < 2; mf++) {
            const int r0 = wm * 32 + mf * 16 + g;
            const float al0 = arow[r0], al1 = arow[r0 + 8];
            #pragma unroll
            for (int nf = 0; nf < 2; nf++) {
                o[mf][nf][0] *= al0; o[mf][nf][1] *= al0;
                o[mf][nf][2] *= al1; o[mf][nf][3] *= al1;
            }
        }
        #pragma unroll
        for (int k8 = 0; k8 < 8; k8++) {
            const int k0 = k8 * 8;
            uint32_t a[2][4], b[2][2];
            #pragma unroll
            for (int mf = 0; mf < 2; mf++) {
                const int rb = wm * 32 + mf * 16;
                a[mf][0] = __float_as_uint(Ss[(rb + g) * ATQ + k0 + qd]);
                a[mf][1] = __float_as_uint(Ss[(rb + g + 8) * ATQ + k0 + qd]);
                a[mf][2] = __float_as_uint(Ss[(rb + g) * ATQ + k0 + 4 + qd]);
                a[mf][3] = __float_as_uint(Ss[(rb + g + 8) * ATQ + k0 + 4 + qd]);
            }
            #pragma unroll
            for (int nf = 0; nf < 2; nf++) {
                const int nb = wn * 16 + nf * 8;
                b[nf][0] = __float_as_uint(Vs[(k0 + qd) * ATV + nb + g]);
                b[nf][1] = __float_as_uint(Vs[(k0 + 4 + qd) * ATV + nb + g]);
            }
            #pragma unroll
            for (int mf = 0; mf < 2; mf++)
                #pragma unroll
                for (int nf = 0; nf < 2; nf++)
                    mma_tf32(o[mf][nf], a[mf], b[nf]);
        }
        __syncthreads();
    }

    #pragma unroll
    for (int mf = 0; mf < 2; mf++) {
        const int r0 = wm * 32 + mf * 16 + g;
        const float li0 = 1.f / lrow[r0];
        const float li1 = 1.f / lrow[r0 + 8];
        #pragma unroll
        for (int nf = 0; nf < 2; nf++) {
            const int col = h * HD + wn * 16 + nf * 8 + 2 * qd;
            store_split2(o2, 2 * O_DIM, qt * 64 + r0, O_DIM, col,
                         o[mf][nf][0] * li0, o[mf][nf][1] * li0);
            store_split2(o2, 2 * O_DIM, qt * 64 + r0 + 8, O_DIM, col,
                         o[mf][nf][2] * li1, o[mf][nf][3] * li1);
        }
    }
}

// ---------------------------------------------------------------------------
// Launch
// ---------------------------------------------------------------------------
static inline int cdiv_i(long long a, int b) { return (int)((a + b - 1) / b); }

extern "C" void kernel_launch(void* const* d_in, const int* in_sizes, int n_in,
                              void* d_out, int out_size)
{
    const float* x        = (const float*)d_in[0];
    const float* an_scale = (const float*)d_in[1];
    const float* wqkv     = (const float*)d_in[2];
    const float* bqkv     = (const float*)d_in[3];
    const float* wout     = (const float*)d_in[4];
    const float* bout     = (const float*)d_in[5];
    const float* mn_scale = (const float*)d_in[6];
    const float* w1       = (const float*)d_in[7];
    const float* b1       = (const float*)d_in[8];
    const float* w2       = (const float*)d_in[9];
    const float* b2       = (const float*)d_in[10];
    float* out = (float*)d_out;

    static float *qkv_p = nullptr, *h_p, *ws_p, *rt_p;
    static __nv_bfloat16 *w2qkv_p, *w2out_p, *w2up_p, *w2dn_p, *a2_p;
    if (!qkv_p) {
        cudaGetSymbolAddress((void**)&qkv_p,  g_qkv);
        cudaGetSymbolAddress((void**)&h_p,    g_h);
        cudaGetSymbolAddress((void**)&ws_p,   g_ws);
        cudaGetSymbolAddress((void**)&rt_p,   g_rope);
        cudaGetSymbolAddress((void**)&w2qkv_p, g_w2_qkv);
        cudaGetSymbolAddress((void**)&w2out_p, g_w2_out);
        cudaGetSymbolAddress((void**)&w2up_p,  g_w2_up);
        cudaGetSymbolAddress((void**)&w2dn_p,  g_w2_dn);
        cudaGetSymbolAddress((void**)&a2_p,    g_a2);
    }
    cudaFuncSetAttribute(attn_mma_kernel,
                         cudaFuncAttributeMaxDynamicSharedMemorySize, ATTN_SMEM);
    cudaFuncSetAttribute(mma_gemm_sk,
                         cudaFuncAttributeMaxDynamicSharedMemorySize, GSMEM_TOTAL);

    // Weight splits + rope table
    convert_split_kernel<<<dim3(cdiv_i(HID / 4, 256), QKV_DIM), 256>>>(
        wqkv, w2qkv_p, QKV_DIM, HID);
    convert_split_kernel<<<dim3(cdiv_i(O_DIM / 4, 256), NPAD_OUT), 256>>>(
        wout, w2out_p, HID, O_DIM);
    convert_split_kernel<<<dim3(cdiv_i(HID / 4, 256), NPAD_UP), 256>>>(
        w1, w2up_p, U_DIM, HID);
    convert_split_kernel<<<dim3(cdiv_i(INTER / 4, 256), NPAD_DN), 256>>>(
        w2, w2dn_p, HID, INTER);
    rope_table_kernel<<<T_TOK, 32>>>(rt_p);

    // 1) attn rmsnorm -> split a2
    rmsnorm_split_kernel<<<T_TOK, 256>>>(x, an_scale, a2_p);

    // 2) QKV GEMM (split-K z=6) + fused reduce+rope
    {
        dim3 grid(T_TOK / 128, QKV_DIM / 256, 6);
        mma_gemm_sk<<<grid, 256, GSMEM_TOTAL>>>(a2_p, w2qkv_p, ws_p, HID, QKV_DIM, 2);
        reduce_qkv_rope_kernel<<<T_TOK, 256>>>(ws_p, bqkv, rt_p, qkv_p);
    }

    // 3) attention (writes split a2, K=4096)
    {
        dim3 grid(T_TOK / 64, NH);
        attn_mma_kernel<<<grid, 256, ATTN_SMEM>>>(qkv_p, a2_p);
    }

    // 4) out GEMM + fused reduce+residual+rmsnorm -> h, split a2
    {
        dim3 grid(T_TOK / 128, NPAD_OUT / 256, 3);
        mma_gemm_sk<<<grid, 256, GSMEM_TOTAL>>>(a2_p, w2out_p, ws_p, O_DIM, NPAD_OUT, 1);
        reduce_out_rms_kernel<<<T_TOK, 256>>>(ws_p, bout, x, mn_scale, h_p, a2_p);
    }

    // 5) MLP up GEMM + fused reduce+act -> split a2
    {
        dim3 grid(T_TOK / 128, NPAD_UP / 256, 3);
        mma_gemm_sk<<<grid, 256, GSMEM_TOTAL>>>(a2_p, w2up_p, ws_p, HID, NPAD_UP, 1);
        dim3 rg(cdiv_i(INTER / 2, 256), T_TOK);
        reduce_up_act_kernel<<<rg, 256>>>(ws_p, b1, a2_p);
    }

    // 6) MLP down GEMM + fused reduce+residual -> out
    {
        dim3 grid(T_TOK / 128, NPAD_DN / 256, 3);
        mma_gemm_sk<<<grid, 256, GSMEM_TOTAL>>>(a2_p, w2dn_p, ws_p, INTER, NPAD_DN, 1);
        reduce_dn_kernel<<<cdiv_i((long long)T_TOK * HID / 4, 256), 256>>>(
            ws_p, b2, h_p, out);
    }
}

// round 10
// speedup vs baseline: 1.8106x; 1.1916x over previous
#include <cuda_runtime.h>
#include <cuda_bf16.h>
#include <math.h>
#include <stdint.h>

// ---------------------------------------------------------------------------
// Problem constants
// ---------------------------------------------------------------------------
#define T_TOK   1024
#define HID     2880
#define NH      64
#define KVH     8
#define HD      64
#define INTER   2880
#define QKV_DIM (HD*(NH+2*KVH))      // 5120
#define O_DIM   (NH*HD)              // 4096
#define U_DIM   (2*INTER)            // 5760
#define SM_SCALE 0.125f
#define EPSF    1e-5f

#define NPAD_OUT 3072
#define NPAD_UP  5888
#define NPAD_DN  3072

// ---------------------------------------------------------------------------
// Scratch
// ---------------------------------------------------------------------------
__device__ float g_qkv[T_TOK * QKV_DIM];
__device__ float g_h  [T_TOK * HID];
__device__ float g_t  [T_TOK * HID];             // post-norm activations (fp32)
__device__ float g_o  [T_TOK * O_DIM];           // attention output (fp32)
__device__ float g_act[T_TOK * INTER];           // swiglu output (fp32)
__device__ float g_ws [6 * T_TOK * QKV_DIM];     // split-K partials
__device__ float g_rope[T_TOK * 64];

__device__ __align__(256) __nv_bfloat16 g_w2_qkv[QKV_DIM * 2 * HID];
__device__ __align__(256) __nv_bfloat16 g_a2    [T_TOK * 2 * HID];

// ---------------------------------------------------------------------------
// PTX helpers
// ---------------------------------------------------------------------------
__device__ __forceinline__ uint32_t smem_u32(const void* p) {
    uint32_t a;
    asm("{ .reg .u64 t; cvta.to.shared.u64 t, %1; cvt.u32.u64 %0, t; }" : "=r"(a) : "l"(p));
    return a;
}
__device__ __forceinline__ void cp16(uint32_t dst, const void* src) {
    asm volatile("cp.async.cg.shared.global [%0], [%1], 16;" :: "r"(dst), "l"(src));
}
__device__ __forceinline__ void cp_commit() {
    asm volatile("cp.async.commit_group;" ::: "memory");
}
__device__ __forceinline__ void cp_wait1() {
    asm volatile("cp.async.wait_group 1;" ::: "memory");
}
__device__ __forceinline__ void cp_wait0() {
    asm volatile("cp.async.wait_group 0;" ::: "memory");
}
__device__ __forceinline__ void ldmatrix_x4(uint32_t& r0, uint32_t& r1,
                                            uint32_t& r2, uint32_t& r3, uint32_t addr) {
    asm volatile("ldmatrix.sync.aligned.m8n8.x4.shared.b16 {%0,%1,%2,%3}, [%4];"
        : "=r"(r0), "=r"(r1), "=r"(r2), "=r"(r3) : "r"(addr));
}
__device__ __forceinline__ void mma_bf16(float& c0, float& c1, float& c2, float& c3,
                                         uint32_t a0, uint32_t a1, uint32_t a2, uint32_t a3,
                                         uint32_t b0, uint32_t b1) {
    asm volatile("mma.sync.aligned.m16n8k16.row.col.f32.bf16.bf16.f32 "
        "{%0,%1,%2,%3}, {%4,%5,%6,%7}, {%8,%9}, {%0,%1,%2,%3};"
        : "+f"(c0), "+f"(c1), "+f"(c2), "+f"(c3)
        : "r"(a0), "r"(a1), "r"(a2), "r"(a3), "r"(b0), "r"(b1));
}
__device__ __forceinline__ void mma_tf32(float* c, const uint32_t* a, const uint32_t* b) {
    asm volatile("mma.sync.aligned.m16n8k8.row.col.f32.tf32.tf32.f32 "
        "{%0,%1,%2,%3}, {%4,%5,%6,%7}, {%8,%9}, {%0,%1,%2,%3};"
        : "+f"(c[0]), "+f"(c[1]), "+f"(c[2]), "+f"(c[3])
        : "r"(a[0]), "r"(a[1]), "r"(a[2]), "r"(a[3]), "r"(b[0]), "r"(b[1]));
}
__device__ __forceinline__ float tf32r(float x) {
    uint32_t o;
    asm("cvt.rna.tf32.f32 %0, %1;" : "=r"(o) : "f"(x));
    return __uint_as_float(o);
}
__device__ __forceinline__ uint32_t tf32u(float x) {
    uint32_t o;
    asm("cvt.rna.tf32.f32 %0, %1;" : "=r"(o) : "f"(x));
    return o;
}

// FMA-pipe exp
__device__ __forceinline__ float fast_exp(float x) {
    x = fmaxf(x, -80.f);
    const float y = x * 1.4426950408889634f;
    const float fn = y + 12582912.f;
    const int ni = __float_as_int(fn) - 0x4B400000;
    const float f = y - (fn - 12582912.f);
    float p = 1.3333558146e-3f;
    p = fmaf(p, f, 9.6181291076e-3f);
    p = fmaf(p, f, 5.5504108664e-2f);
    p = fmaf(p, f, 2.4022650696e-1f);
    p = fmaf(p, f, 6.9314718056e-1f);
    p = fmaf(p, f, 1.0f);
    return p * __int_as_float((ni + 127) << 23);
}

// ---------------------------------------------------------------------------
// fp32 -> [hi | lo] bf16 split conversion (qkv weights only)
// ---------------------------------------------------------------------------
__global__ __launch_bounds__(256) void convert_split_kernel(
    const float* __restrict__ X, __nv_bfloat16* __restrict__ X2,
    int Nrows, int K)
{
    const int n = blockIdx.y;
    const int k = (blockIdx.x * 256 + threadIdx.x) * 4;
    if (k >= K) return;
    float4 v = make_float4(0.f, 0.f, 0.f, 0.f);
    if (n < Nrows) v = *(const float4*)(X + (size_t)n * K + k);
    __nv_bfloat16 hx = __float2bfloat16(v.x);
    __nv_bfloat16 hy = __float2bfloat16(v.y);
    __nv_bfloat16 hz = __float2bfloat16(v.z);
    __nv_bfloat16 hw = __float2bfloat16(v.w);
    float lx = v.x - __bfloat162float(hx);
    float ly = v.y - __bfloat162float(hy);
    float lz = v.z - __bfloat162float(hz);
    float lw = v.w - __bfloat162float(hw);
    __nv_bfloat16* row = X2 + (size_t)n * 2 * K;
    __nv_bfloat162* ph = (__nv_bfloat162*)(row + k);
    ph[0] = __halves2bfloat162(hx, hy);
    ph[1] = __halves2bfloat162(hz, hw);
    __nv_bfloat162* pl = (__nv_bfloat162*)(row + K + k);
    pl[0] = __floats2bfloat162_rn(lx, ly);
    pl[1] = __floats2bfloat162_rn(lz, lw);
}

// ---------------------------------------------------------------------------
// Split-bf16 GEMM, split-K (3 segments x S sub-slices): partials -> ws.
// (qkv only)  grid (M/128, Npad/256, 3*S)
// ---------------------------------------------------------------------------
#define KSTRIDE_B 144
#define ATILE_B  (128 * KSTRIDE_B)
#define BTILE_B  (256 * KSTRIDE_B)
#define GSMEM_TOTAL (2 * ATILE_B + 2 * BTILE_B)

__device__ __forceinline__ void fill_tiles_mma(
    uint32_t aT, uint32_t bT,
    const __nv_bfloat16* __restrict__ A2, const __nv_bfloat16* __restrict__ W2,
    int Kp, int m0, int n0, int ka, int kw, int tid)
{
    #pragma unroll
    for (int i = 0; i < 4; i++) {
        int q = tid + 256 * i;
        int r = q >> 3, c = q & 7;
        cp16(aT + r * KSTRIDE_B + c * 16, A2 + (size_t)(m0 + r) * Kp + ka + c * 8);
    }
    #pragma unroll
    for (int i = 0; i < 8; i++) {
        int q = tid + 256 * i;
        int r = q >> 3, c = q & 7;
        cp16(bT + r * KSTRIDE_B + c * 16, W2 + (size_t)(n0 + r) * Kp + kw + c * 8);
    }
}

__global__ __launch_bounds__(256) void mma_gemm_sk(
    const __nv_bfloat16* __restrict__ A2, const __nv_bfloat16* __restrict__ W2,
    float* __restrict__ ws, int K, int Npad, int S)
{
    extern __shared__ char smem[];
    const uint32_t sbase = smem_u32(smem);
    const uint32_t tA[2] = { sbase,                sbase + ATILE_B };
    const uint32_t tB[2] = { sbase + 2 * ATILE_B,  sbase + 2 * ATILE_B + BTILE_B };

    const int tid  = threadIdx.x;
    const int wid  = tid >> 5;
    const int lane = tid & 31;
    const int wm   = wid >> 2;
    const int wn   = wid & 3;
    const int m0 = blockIdx.x * 128;
    const int n0 = blockIdx.y * 256;
    const int z  = blockIdx.z;
    const int seg = z / S;
    const int sub = z - seg * S;
    const int Kp = 2 * K;
    const int NCseg = K >> 6;
    const int cb = (sub * NCseg) / S;
    const int ce = ((sub + 1) * NCseg) / S;

    const int kaBase = (seg == 2) ? K : 0;
    const int kwBase = (seg == 1) ? K : 0;

    const uint32_t aOff = (uint32_t)((wm * 64 + (lane & 15)) * KSTRIDE_B + (lane >> 4) * 16);
    const uint32_t bOff = (uint32_t)((wn * 64 + (lane & 7) + ((lane >> 4) & 1) * 8) * KSTRIDE_B
                                     + ((lane >> 3) & 1) * 16);

    float acc[4][8][4];
    #pragma unroll
    for (int i = 0; i < 4; i++)
        #pragma unroll
        for (int j = 0; j < 8; j++)
            #pragma unroll
            for (int q = 0; q < 4; q++) acc[i][j][q] = 0.f;

    fill_tiles_mma(tA[0], tB[0], A2, W2, Kp, m0, n0,
                   kaBase + (cb << 6), kwBase + (cb << 6), tid);
    cp_commit();

    for (int c = cb; c < ce; c++) {
        const int b = (c - cb) & 1;
        if (c + 1 < ce) {
            const int nb = (c + 1 - cb) & 1;
            const int kk = (c + 1) << 6;
            fill_tiles_mma(tA[nb], tB[nb], A2, W2, Kp, m0, n0,
                           kaBase + kk, kwBase + kk, tid);
            cp_commit();
            cp_wait1();
        } else {
            cp_wait0();
        }
        __syncthreads();

        #pragma unroll
        for (int ks = 0; ks < 4; ks++) {
            const uint32_t kb = (uint32_t)(ks * 32);
            uint32_t a[4][4];
            #pragma unroll
            for (int mf = 0; mf < 4; mf++)
                ldmatrix_x4(a[mf][0], a[mf][1], a[mf][2], a[mf][3],
                            tA[b] + aOff + mf * 16 * KSTRIDE_B + kb);
            uint32_t bb[8][2];
            #pragma unroll
            for (int bf = 0; bf < 4; bf++) {
                uint32_t r0, r1, r2, r3;
                ldmatrix_x4(r0, r1, r2, r3,
                            tB[b] + bOff + bf * 16 * KSTRIDE_B + kb);
                bb[bf * 2 + 0][0] = r0; bb[bf * 2 + 0][1] = r1;
                bb[bf * 2 + 1][0] = r2; bb[bf * 2 + 1][1] = r3;
            }
            #pragma unroll
            for (int mf = 0; mf < 4; mf++)
                #pragma unroll
                for (int nf = 0; nf < 8; nf++)
                    mma_bf16(acc[mf][nf][0], acc[mf][nf][1],
                             acc[mf][nf][2], acc[mf][nf][3],
                             a[mf][0], a[mf][1], a[mf][2], a[mf][3],
                             bb[nf][0], bb[nf][1]);
        }
        __syncthreads();
    }

    float* wz = ws + (size_t)z * T_TOK * Npad;
    const int g = lane >> 2;
    const int t = lane & 3;
    #pragma unroll
    for (int nf = 0; nf < 8; nf++) {
        const int col = n0 + wn * 64 + nf * 8 + t * 2;
        #pragma unroll
        for (int mf = 0; mf < 4; mf++) {
            const int r0 = m0 + wm * 64 + mf * 16 + g;
            *(float2*)(wz + (size_t)r0 * Npad + col) =
                make_float2(acc[mf][nf][0], acc[mf][nf][1]);
            *(float2*)(wz + (size_t)(r0 + 8) * Npad + col) =
                make_float2(acc[mf][nf][2], acc[mf][nf][3]);
        }
    }
}

// ---------------------------------------------------------------------------
// tf32 single-pass GEMM, split-K S slices: raw fp32 A & W, in-reg tf32 round.
// 128x256 CTA tile, BK=32 floats, double-buffered cp.async.
// smem row = 32 floats + 4 pad (144B). grid (M/128, Npad/256, S)
// ---------------------------------------------------------------------------
#define NF32 36    // floats per smem row
#define A_F  4608  // floats per A tile (128*36)
#define B_F  9216  // floats per B tile (256*36)

__device__ __forceinline__ void fill_tiles_tf32(
    uint32_t aT, uint32_t bT,
    const float* __restrict__ A, const float* __restrict__ W,
    int K, int m0, int n0, int k0, int Nrows, int tid)
{
    #pragma unroll
    for (int i = 0; i < 4; i++) {
        int q = tid + 256 * i;
        int r = q >> 3, c = q & 7;
        cp16(aT + r * 144 + c * 16, A + (size_t)(m0 + r) * K + k0 + c * 4);
    }
    #pragma unroll
    for (int i = 0; i < 8; i++) {
        int q = tid + 256 * i;
        int r = q >> 3, c = q & 7;
        int rw = n0 + r; if (rw >= Nrows) rw = Nrows - 1;
        cp16(bT + r * 144 + c * 16, W + (size_t)rw * K + k0 + c * 4);
    }
}

__global__ __launch_bounds__(256) void tf32_gemm_sk(
    const float* __restrict__ A, const float* __restrict__ W,
    float* __restrict__ ws, int K, int Npad, int Nrows, int S)
{
    extern __shared__ char smem[];
    const uint32_t sbase = smem_u32(smem);
    const uint32_t tA[2] = { sbase,               sbase + A_F * 4 };
    const uint32_t tB[2] = { sbase + 2 * A_F * 4, sbase + 2 * A_F * 4 + B_F * 4 };
    float* smf = (float*)smem;

    const int tid  = threadIdx.x;
    const int wid  = tid >> 5;
    const int lane = tid & 31;
    const int wm   = wid >> 2;
    const int wn   = wid & 3;
    const int g    = lane >> 2;
    const int qd   = lane & 3;
    const int m0 = blockIdx.x * 128;
    const int n0 = blockIdx.y * 256;
    const int z  = blockIdx.z;
    const int NC = K >> 5;
    const int cb = (z * NC) / S;
    const int ce = ((z + 1) * NC) / S;

    float acc[4][8][4];
    #pragma unroll
    for (int i = 0; i < 4; i++)
        #pragma unroll
        for (int j = 0; j < 8; j++)
            #pragma unroll
            for (int q = 0; q < 4; q++) acc[i][j][q] = 0.f;

    fill_tiles_tf32(tA[0], tB[0], A, W, K, m0, n0, cb << 5, Nrows, tid);
    cp_commit();

    for (int c = cb; c < ce; c++) {
        const int b = (c - cb) & 1;
        if (c + 1 < ce) {
            const int nb = (c + 1 - cb) & 1;
            fill_tiles_tf32(tA[nb], tB[nb], A, W, K, m0, n0,
                            (c + 1) << 5, Nrows, tid);
            cp_commit();
            cp_wait1();
        } else {
            cp_wait0();
        }
        __syncthreads();

        const float* As = smf + b * A_F;
        const float* Bs = smf + 2 * A_F + b * B_F;

        #pragma unroll
        for (int ks = 0; ks < 4; ks++) {
            const int k0 = ks * 8;
            uint32_t a[4][4], bb[8][2];
            #pragma unroll
            for (int mf = 0; mf < 4; mf++) {
                const int row = wm * 64 + mf * 16 + g;
                a[mf][0] = tf32u(As[row * NF32 + k0 + qd]);
                a[mf][1] = tf32u(As[(row + 8) * NF32 + k0 + qd]);
                a[mf][2] = tf32u(As[row * NF32 + k0 + 4 + qd]);
                a[mf][3] = tf32u(As[(row + 8) * NF32 + k0 + 4 + qd]);
            }
            #pragma unroll
            for (int nf = 0; nf < 8; nf++) {
                const int rowb = wn * 64 + nf * 8 + g;
                bb[nf][0] = tf32u(Bs[rowb * NF32 + k0 + qd]);
                bb[nf][1] = tf32u(Bs[rowb * NF32 + k0 + 4 + qd]);
            }
            #pragma unroll
            for (int mf = 0; mf < 4; mf++)
                #pragma unroll
                for (int nf = 0; nf < 8; nf++)
                    mma_tf32(acc[mf][nf], a[mf], bb[nf]);
        }
        __syncthreads();
    }

    float* wz = ws + (size_t)z * T_TOK * Npad;
    const int t = lane & 3;
    #pragma unroll
    for (int nf = 0; nf < 8; nf++) {
        const int col = n0 + wn * 64 + nf * 8 + t * 2;
        #pragma unroll
        for (int mf = 0; mf < 4; mf++) {
            const int r0 = m0 + wm * 64 + mf * 16 + g;
            *(float2*)(wz + (size_t)r0 * Npad + col) =
                make_float2(acc[mf][nf][0], acc[mf][nf][1]);
            *(float2*)(wz + (size_t)(r0 + 8) * Npad + col) =
                make_float2(acc[mf][nf][2], acc[mf][nf][3]);
        }
    }
}

// ---------------------------------------------------------------------------
// Rope table
// ---------------------------------------------------------------------------
__global__ void rope_table_kernel(float* __restrict__ tab)
{
    const int t = blockIdx.x;
    const int i = threadIdx.x;
    const float PI = 3.14159265358979323846f;
    const float rope_base = 150000.f;
    const float freq = powf(rope_base, (float)i / 32.f);
    const float conc = 0.1f * logf(32.f) + 1.f;
    const float lg = logf(rope_base);
    const float low  = 32.f * logf(4096.f / (32.f * 2.f * PI)) / lg;
    const float high = 32.f * logf(4096.f / (2.f * PI)) / lg;
    const float interp = 1.f / (32.f * freq);
    const float extrap = 1.f / freq;
    float ramp = ((float)i - low) / (high - low);
    ramp = fminf(fmaxf(ramp, 0.f), 1.f);
    const float mask = 1.f - ramp;
    const float invf = interp * (1.f - mask) + extrap * mask;
    const float ang = (float)t * invf;
    tab[t * 64 + i]      = cosf(ang) * conc;
    tab[t * 64 + 32 + i] = sinf(ang) * conc;
}

// ---------------------------------------------------------------------------
// QKV reduce (6 slices) + bias + RoPE -> qkv
// ---------------------------------------------------------------------------
__global__ __launch_bounds__(256) void reduce_qkv_rope_kernel(
    const float* __restrict__ ws, const float* __restrict__ bias,
    const float* __restrict__ tab, float* __restrict__ qkv)
{
    const int t = blockIdx.x;
    const int tid = threadIdx.x;
    const size_t SL = (size_t)T_TOK * QKV_DIM;
    const float* base = ws + (size_t)t * QKV_DIM;
    float* outr = qkv + (size_t)t * QKV_DIM;
    const float* tr = tab + t * 64;

    for (int p = tid; p < 72 * 32; p += 256) {
        const int head = p >> 5, d = p & 31;
        const int c1 = head * 64 + d, c2 = c1 + 32;
        float s1 = bias[c1], s2 = bias[c2];
        #pragma unroll
        for (int z = 0; z < 6; z++) {
            s1 += base[z * SL + c1];
            s2 += base[z * SL + c2];
        }
        const float cc = tr[d], ss = tr[32 + d];
        outr[c1] = s1 * cc - s2 * ss;
        outr[c2] = s2 * cc + s1 * ss;
    }
    for (int c = 4608 + tid; c < QKV_DIM; c += 256) {
        float s = bias[c];
        #pragma unroll
        for (int z = 0; z < 6; z++) s += base[z * SL + c];
        outr[c] = s;
    }
}

// ---------------------------------------------------------------------------
// out reduce (3) + bias + residual -> h, then rmsnorm -> fp32 g_t
// ---------------------------------------------------------------------------
__global__ __launch_bounds__(256) void reduce_out_rms_kernel(
    const float* __restrict__ ws, const float* __restrict__ bias,
    const float* __restrict__ res, const float* __restrict__ scale,
    float* __restrict__ h, float* __restrict__ tn)
{
    __shared__ float row[HID];
    __shared__ float red[256];
    const int t = blockIdx.x;
    const int tid = threadIdx.x;
    const size_t SL = (size_t)T_TOK * NPAD_OUT;
    const float* base = ws + (size_t)t * NPAD_OUT;
    const float* xr = res + (size_t)t * HID;
    float* hr = h + (size_t)t * HID;

    float sq = 0.f;
    for (int c = tid * 4; c < HID; c += 1024) {
        const float4 a = *(const float4*)(base + c);
        const float4 b = *(const float4*)(base + SL + c);
        const float4 d = *(const float4*)(base + 2 * SL + c);
        const float4 bb = *(const float4*)(bias + c);
        const float4 rv = *(const float4*)(xr + c);
        float4 v;
        v.x = a.x + b.x + d.x + bb.x + rv.x;
        v.y = a.y + b.y + d.y + bb.y + rv.y;
        v.z = a.z + b.z + d.z + bb.z + rv.z;
        v.w = a.w + b.w + d.w + bb.w + rv.w;
        *(float4*)(row + c) = v;
        *(float4*)(hr + c) = v;
        sq += v.x * v.x + v.y * v.y + v.z * v.z + v.w * v.w;
    }
    red[tid] = sq;
    __syncthreads();
    for (int off = 128; off > 0; off >>= 1) {
        if (tid < off) red[tid] += red[tid + off];
        __syncthreads();
    }
    const float inv = rsqrtf(red[0] / (float)HID + EPSF);
    float* tr = tn + (size_t)t * HID;
    for (int c = tid * 4; c < HID; c += 1024) {
        float4 v = *(const float4*)(row + c);
        float4 sc = *(const float4*)(scale + c);
        v.x *= inv * sc.x; v.y *= inv * sc.y;
        v.z *= inv * sc.z; v.w *= inv * sc.w;
        *(float4*)(tr + c) = v;
    }
}

// ---------------------------------------------------------------------------
// up reduce (3) + bias + clamped SwiGLU -> fp32 g_act
// ---------------------------------------------------------------------------
__global__ __launch_bounds__(256) void reduce_up_act_kernel(
    const float* __restrict__ ws, const float* __restrict__ bias,
    float* __restrict__ act)
{
    const int t = blockIdx.y;
    const int j = blockIdx.x * 256 + threadIdx.x;   // 0..1439
    if (j >= INTER / 2) return;
    const int c = j * 4;
    const size_t SL = (size_t)T_TOK * NPAD_UP;
    const float* base = ws + (size_t)t * NPAD_UP + c;
    const float4 a = *(const float4*)base;
    const float4 b = *(const float4*)(base + SL);
    const float4 d = *(const float4*)(base + 2 * SL);
    const float4 bb = *(const float4*)(bias + c);
    float u0 = a.x + b.x + d.x + bb.x;
    float u1 = a.y + b.y + d.y + bb.y;
    float u2 = a.z + b.z + d.z + bb.z;
    float u3 = a.w + b.w + d.w + bb.w;

    float g0 = fminf(u0, 7.f), l0 = fminf(fmaxf(u1, -7.f), 7.f);
    float g1 = fminf(u2, 7.f), l1 = fminf(fmaxf(u3, -7.f), 7.f);
    const float v0 = g0 / (1.f + fast_exp(-1.702f * g0)) * (l0 + 1.f);
    const float v1 = g1 / (1.f + fast_exp(-1.702f * g1)) * (l1 + 1.f);

    *(float2*)(act + (size_t)t * INTER + 2 * j) = make_float2(v0, v1);
}

// ---------------------------------------------------------------------------
// dn reduce (3) + bias + residual -> out (final)
// ---------------------------------------------------------------------------
__global__ __launch_bounds__(256) void reduce_dn_kernel(
    const float* __restrict__ ws, const float* __restrict__ bias,
    const float* __restrict__ res, float* __restrict__ C)
{
    const int idx = blockIdx.x * 256 + threadIdx.x;
    const int q = HID >> 2;
    if (idx >= T_TOK * q) return;
    const int m = idx / q;
    const int col = (idx - m * q) * 4;
    const size_t SL = (size_t)T_TOK * NPAD_DN;
    const float* p = ws + (size_t)m * NPAD_DN + col;
    const float4 a = *(const float4*)p;
    const float4 b = *(const float4*)(p + SL);
    const float4 c = *(const float4*)(p + 2 * SL);
    const float4 bb = *(const float4*)(bias + col);
    const float4 r = *(const float4*)(res + (size_t)m * HID + col);
    float4 v;
    v.x = a.x + b.x + c.x + bb.x + r.x;
    v.y = a.y + b.y + c.y + bb.y + r.y;
    v.z = a.z + b.z + c.z + bb.z + r.z;
    v.w = a.w + b.w + c.w + bb.w + r.w;
    *(float4*)(C + (size_t)m * HID + col) = v;
}

// ---------------------------------------------------------------------------
// RMSNorm -> split-bf16 (first norm, on x; feeds bf16 qkv GEMM)
// ---------------------------------------------------------------------------
__global__ __launch_bounds__(256) void rmsnorm_split_kernel(
    const float* __restrict__ x, const float* __restrict__ scale,
    __nv_bfloat16* __restrict__ a2)
{
    const int row = blockIdx.x;
    const float* xr = x + (size_t)row * HID;
    float s = 0.f;
    for (int i = threadIdx.x; i < HID; i += 256) { float v = xr[i]; s += v * v; }
    __shared__ float red[256];
    red[threadIdx.x] = s;
    __syncthreads();
    for (int off = 128; off > 0; off >>= 1) {
        if (threadIdx.x < off) red[threadIdx.x] += red[threadIdx.x + off];
        __syncthreads();
    }
    const float inv = rsqrtf(red[0] / (float)HID + EPSF);
    __nv_bfloat16* rowp = a2 + (size_t)row * 2 * HID;
    for (int i = threadIdx.x * 2; i < HID; i += 512) {
        float v0 = xr[i] * inv * scale[i];
        float v1 = xr[i + 1] * inv * scale[i + 1];
        __nv_bfloat16 h0 = __float2bfloat16(v0), h1 = __float2bfloat16(v1);
        *(__nv_bfloat162*)(rowp + i) = __halves2bfloat162(h0, h1);
        *(__nv_bfloat162*)(rowp + HID + i) = __floats2bfloat162_rn(
            v0 - __bfloat162float(h0), v1 - __bfloat162float(h1));
    }
}

// ---------------------------------------------------------------------------
// Causal GQA flash attention (tf32 mma + FMA-pipe exp), fp32 output
// ---------------------------------------------------------------------------
#define ATQ 68
#define ATV 72
#define ATTN_SMEM ((3 * 64 * ATQ + 64 * ATV + 3 * 64 + 2 * 256) * (int)sizeof(float))

__global__ __launch_bounds__(256) void attn_mma_kernel(
    const float* __restrict__ qkv, float* __restrict__ og)
{
    extern __shared__ float sm[];
    float* Qs   = sm;
    float* Ks   = Qs + 64 * ATQ;
    float* Ss   = Ks + 64 * ATQ;
    float* Vs   = Ss + 64 * ATQ;
    float* mrow = Vs + 64 * ATV;
    float* lrow = mrow + 64;
    float* arow = lrow + 64;
    float* pm   = arow + 64;
    float* ps   = pm + 256;

    const int qt = blockIdx.x, h = blockIdx.y, kh = h >> 3;
    const int tid = threadIdx.x, wid = tid >> 5, lane = tid & 31;
    const int wm = wid >> 2, wn = wid & 3;
    const int g = lane >> 2, qd = lane & 3;
    const int sr = tid & 63, sq = tid >> 6;

    for (int i = tid; i < 64 * 64; i += 256) {
        int r = i >> 6, d = i & 63;
        Qs[r * ATQ + d] = tf32r(qkv[(size_t)(qt * 64 + r) * QKV_DIM + h * HD + d]);
    }
    if (tid < 64) { mrow[tid] = -1e30f; lrow[tid] = 0.f; }
    float o[2][2][4];
    #pragma unroll
    for (int i = 0; i < 2; i++)
        #pragma unroll
        for (int j = 0; j < 2; j++)
            #pragma unroll
            for (int q = 0; q < 4; q++) o[i][j][q] = 0.f;
    __syncthreads();

    for (int kt = 0; kt <= qt; kt++) {
        for (int i = tid; i < 64 * 64; i += 256) {
            int r = i >> 6, d = i & 63;
            size_t base = (size_t)(kt * 64 + r) * QKV_DIM;
            Ks[r * ATQ + d] = tf32r(qkv[base + NH * HD + kh * HD + d]);
            Vs[r * ATV + d] = tf32r(qkv[base + (NH + KVH) * HD + kh * HD + d]);
        }
        __syncthreads();

        float s[2][2][4];
        #pragma unroll
        for (int i = 0; i < 2; i++)
            #pragma unroll
            for (int j = 0; j < 2; j++)
                #pragma unroll
                for (int q = 0; q < 4; q++) s[i][j][q] = 0.f;
        #pragma unroll
        for (int k8 = 0; k8 < 8; k8++) {
            const int k0 = k8 * 8;
            uint32_t a[2][4], b[2][2];
            #pragma unroll
            for (int mf = 0; mf < 2; mf++) {
                const int rb = wm * 32 + mf * 16;
                a[mf][0] = __float_as_uint(Qs[(rb + g) * ATQ + k0 + qd]);
                a[mf][1] = __float_as_uint(Qs[(rb + g + 8) * ATQ + k0 + qd]);
                a[mf][2] = __float_as_uint(Qs[(rb + g) * ATQ + k0 + 4 + qd]);
                a[mf][3] = __float_as_uint(Qs[(rb + g + 8) * ATQ + k0 + 4 + qd]);
            }
            #pragma unroll
            for (int nf = 0; nf < 2; nf++) {
                const int nb = wn * 16 + nf * 8;
                b[nf][0] = __float_as_uint(Ks[(nb + g) * ATQ + k0 + qd]);
                b[nf][1] = __float_as_uint(Ks[(nb + g) * ATQ + k0 + 4 + qd]);
            }
            #pragma unroll
            for (int mf = 0; mf < 2; mf++)
                #pragma unroll
                for (int nf = 0; nf < 2; nf++)
                    mma_tf32(s[mf][nf], a[mf], b[nf]);
        }
        #pragma unroll
        for (int mf = 0; mf < 2; mf++)
            #pragma unroll
            for (int nf = 0; nf < 2; nf++) {
                const int r0 = wm * 32 + mf * 16 + g;
                const int c0 = wn * 16 + nf * 8 + 2 * qd;
                *(float2*)&Ss[r0 * ATQ + c0] =
                    make_float2(s[mf][nf][0] * SM_SCALE, s[mf][nf][1] * SM_SCALE);
                *(float2*)&Ss[(r0 + 8) * ATQ + c0] =
                    make_float2(s[mf][nf][2] * SM_SCALE, s[mf][nf][3] * SM_SCALE);
            }
        __syncthreads();

        {
            const int cmax = (kt == qt) ? (sr + 1) : 64;
            const int c0 = sq * 16;
            float mx = -1e30f;
            #pragma unroll
            for (int c = c0; c < c0 + 16; c++)
                if (c < cmax) mx = fmaxf(mx, Ss[sr * ATQ + c]);
            pm[sq * 64 + sr] = mx;
            __syncthreads();
            const float mold = mrow[sr];
            const float mfin = fmaxf(mold,
                fmaxf(fmaxf(pm[sr], pm[64 + sr]), fmaxf(pm[128 + sr], pm[192 + sr])));
            float sum = 0.f;
            #pragma unroll
            for (int c = c0; c < c0 + 16; c++) {
                float p = (c < cmax) ? fast_exp(Ss[sr * ATQ + c] - mfin) : 0.f;
                Ss[sr * ATQ + c] = tf32r(p);
                sum += p;
            }
            ps[sq * 64 + sr] = sum;
            __syncthreads();
            if (sq == 0) {
                const float alpha = fast_exp(mold - mfin);
                mrow[sr] = mfin;
                lrow[sr] = lrow[sr] * alpha
                         + ps[sr] + ps[64 + sr] + ps[128 + sr] + ps[192 + sr];
                arow[sr] = alpha;
            }
            __syncthreads();
        }

        #pragma unroll
        for (int mf = 0; mf < 2; mf++) {
            const int r0 = wm * 32 + mf * 16 + g;
            const float al0 = arow[r0], al1 = arow[r0 + 8];
            #pragma unroll
            for (int nf = 0; nf < 2; nf++) {
                o[mf][nf][0] *= al0; o[mf][nf][1] *= al0;
                o[mf][nf][2] *= al1; o[mf][nf][3] *= al1;
            }
        }
        #pragma unroll
        for (int k8 = 0; k8 < 8; k8++) {
            const int k0 = k8 * 8;
            uint32_t a[2][4], b[2][2];
            #pragma unroll
            for (int mf = 0; mf < 2; mf++) {
                const int rb = wm * 32 + mf * 16;
                a[mf][0] = __float_as_uint(Ss[(rb + g) * ATQ + k0 + qd]);
                a[mf][1] = __float_as_uint(Ss[(rb + g + 8) * ATQ + k0 + qd]);
                a[mf][2] = __float_as_uint(Ss[(rb + g) * ATQ + k0 + 4 + qd]);
                a[mf][3] = __float_as_uint(Ss[(rb + g + 8) * ATQ + k0 + 4 + qd]);
            }
            #pragma unroll
            for (int nf = 0; nf < 2; nf++) {
                const int nb = wn * 16 + nf * 8;
                b[nf][0] = __float_as_uint(Vs[(k0 + qd) * ATV + nb + g]);
                b[nf][1] = __float_as_uint(Vs[(k0 + 4 + qd) * ATV + nb + g]);
            }
            #pragma unroll
            for (int mf = 0; mf < 2; mf++)
                #pragma unroll
                for (int nf = 0; nf < 2; nf++)
                    mma_tf32(o[mf][nf], a[mf], b[nf]);
        }
        __syncthreads();
    }

    #pragma unroll
    for (int mf = 0; mf < 2; mf++) {
        const int r0 = wm * 32 + mf * 16 + g;
        const float li0 = 1.f / lrow[r0];
        const float li1 = 1.f / lrow[r0 + 8];
        #pragma unroll
        for (int nf = 0; nf < 2; nf++) {
            const int col = h * HD + wn * 16 + nf * 8 + 2 * qd;
            *(float2*)(og + (size_t)(qt * 64 + r0) * O_DIM + col) =
                make_float2(o[mf][nf][0] * li0, o[mf][nf][1] * li0);
            *(float2*)(og + (size_t)(qt * 64 + r0 + 8) * O_DIM + col) =
                make_float2(o[mf][nf][2] * li1, o[mf][nf][3] * li1);
        }
    }
}

// ---------------------------------------------------------------------------
// Launch
// ---------------------------------------------------------------------------
static inline int cdiv_i(long long a, int b) { return (int)((a + b - 1) / b); }

extern "C" void kernel_launch(void* const* d_in, const int* in_sizes, int n_in,
                              void* d_out, int out_size)
{
    const float* x        = (const float*)d_in[0];
    const float* an_scale = (const float*)d_in[1];
    const float* wqkv     = (const float*)d_in[2];
    const float* bqkv     = (const float*)d_in[3];
    const float* wout     = (const float*)d_in[4];
    const float* bout     = (const float*)d_in[5];
    const float* mn_scale = (const float*)d_in[6];
    const float* w1       = (const float*)d_in[7];
    const float* b1       = (const float*)d_in[8];
    const float* w2       = (const float*)d_in[9];
    const float* b2       = (const float*)d_in[10];
    float* out = (float*)d_out;

    static float *qkv_p = nullptr, *h_p, *t_p, *o_p, *act_p, *ws_p, *rt_p;
    static __nv_bfloat16 *w2qkv_p, *a2_p;
    if (!qkv_p) {
        cudaGetSymbolAddress((void**)&qkv_p,  g_qkv);
        cudaGetSymbolAddress((void**)&h_p,    g_h);
        cudaGetSymbolAddress((void**)&t_p,    g_t);
        cudaGetSymbolAddress((void**)&o_p,    g_o);
        cudaGetSymbolAddress((void**)&act_p,  g_act);
        cudaGetSymbolAddress((void**)&ws_p,   g_ws);
        cudaGetSymbolAddress((void**)&rt_p,   g_rope);
        cudaGetSymbolAddress((void**)&w2qkv_p, g_w2_qkv);
        cudaGetSymbolAddress((void**)&a2_p,    g_a2);
    }
    cudaFuncSetAttribute(attn_mma_kernel,
                         cudaFuncAttributeMaxDynamicSharedMemorySize, ATTN_SMEM);
    cudaFuncSetAttribute(mma_gemm_sk,
                         cudaFuncAttributeMaxDynamicSharedMemorySize, GSMEM_TOTAL);
    cudaFuncSetAttribute(tf32_gemm_sk,
                         cudaFuncAttributeMaxDynamicSharedMemorySize, GSMEM_TOTAL);

    // qkv weight split + rope table
    convert_split_kernel<<<dim3(cdiv_i(HID / 4, 256), QKV_DIM), 256>>>(
        wqkv, w2qkv_p, QKV_DIM, HID);
    rope_table_kernel<<<T_TOK, 32>>>(rt_p);

    // 1) attn rmsnorm -> split a2 (bf16)
    rmsnorm_split_kernel<<<T_TOK, 256>>>(x, an_scale, a2_p);

    // 2) QKV GEMM (split-bf16, z=6) + fused reduce+rope
    {
        dim3 grid(T_TOK / 128, QKV_DIM / 256, 6);
        mma_gemm_sk<<<grid, 256, GSMEM_TOTAL>>>(a2_p, w2qkv_p, ws_p, HID, QKV_DIM, 2);
        reduce_qkv_rope_kernel<<<T_TOK, 256>>>(ws_p, bqkv, rt_p, qkv_p);
    }

    // 3) attention -> fp32 o
    {
        dim3 grid(T_TOK / 64, NH);
        attn_mma_kernel<<<grid, 256, ATTN_SMEM>>>(qkv_p, o_p);
    }

    // 4) out GEMM (tf32 single pass, S=3) + fused reduce+residual+rmsnorm
    {
        dim3 grid(T_TOK / 128, NPAD_OUT / 256, 3);
        tf32_gemm_sk<<<grid, 256, GSMEM_TOTAL>>>(o_p, wout, ws_p,
                                                 O_DIM, NPAD_OUT, HID, 3);
        reduce_out_rms_kernel<<<T_TOK, 256>>>(ws_p, bout, x, mn_scale, h_p, t_p);
    }

    // 5) MLP up GEMM (tf32, S=3) + fused reduce+act
    {
        dim3 grid(T_TOK / 128, NPAD_UP / 256, 3);
        tf32_gemm_sk<<<grid, 256, GSMEM_TOTAL>>>(t_p, w1, ws_p,
                                                 HID, NPAD_UP, U_DIM, 3);
        dim3 rg(cdiv_i(INTER / 2, 256), T_TOK);
        reduce_up_act_kernel<<<rg, 256>>>(ws_p, b1, act_p);
    }

    // 6) MLP down GEMM (tf32, S=3) + fused reduce+residual -> out
    {
        dim3 grid(T_TOK / 128, NPAD_DN / 256, 3);
        tf32_gemm_sk<<<grid, 256, GSMEM_TOTAL>>>(act_p, w2, ws_p,
                                                 INTER, NPAD_DN, HID, 3);
        reduce_dn_kernel<<<cdiv_i((long long)T_TOK * HID / 4, 256), 256>>>(
            ws_p, b2, h_p, out);
    }
}

// round 11
// speedup vs baseline: 1.9614x; 1.0833x over previous
#include <cuda_runtime.h>
#include <cuda_bf16.h>
#include <math.h>
#include <stdint.h>

// ---------------------------------------------------------------------------
// Problem constants
// ---------------------------------------------------------------------------
#define T_TOK   1024
#define HID     2880
#define NH      64
#define KVH     8
#define HD      64
#define INTER   2880
#define QKV_DIM (HD*(NH+2*KVH))      // 5120
#define O_DIM   (NH*HD)              // 4096
#define U_DIM   (2*INTER)            // 5760
#define SM_SCALE 0.125f
#define EPSF    1e-5f

#define NPAD_OUT 3072
#define NPAD_UP  5888
#define NPAD_DN  3072

// ---------------------------------------------------------------------------
// Scratch
// ---------------------------------------------------------------------------
__device__ float g_qkv[T_TOK * QKV_DIM];
__device__ float g_h  [T_TOK * HID];
__device__ float g_t  [T_TOK * HID];             // post-norm activations (fp32)
__device__ float g_o  [T_TOK * O_DIM];           // attention output (fp32)
__device__ float g_act[T_TOK * INTER];           // swiglu output (fp32)
__device__ float g_ws [6 * T_TOK * QKV_DIM];     // split-K partials
__device__ float g_rope[T_TOK * 64];

// ---------------------------------------------------------------------------
// PTX helpers
// ---------------------------------------------------------------------------
__device__ __forceinline__ uint32_t smem_u32(const void* p) {
    uint32_t a;
    asm("{ .reg .u64 t; cvta.to.shared.u64 t, %1; cvt.u32.u64 %0, t; }" : "=r"(a) : "l"(p));
    return a;
}
__device__ __forceinline__ void cp16(uint32_t dst, const void* src) {
    asm volatile("cp.async.cg.shared.global [%0], [%1], 16;" :: "r"(dst), "l"(src));
}
__device__ __forceinline__ void cp_commit() {
    asm volatile("cp.async.commit_group;" ::: "memory");
}
__device__ __forceinline__ void cp_wait1() {
    asm volatile("cp.async.wait_group 1;" ::: "memory");
}
__device__ __forceinline__ void cp_wait0() {
    asm volatile("cp.async.wait_group 0;" ::: "memory");
}
__device__ __forceinline__ void mma_tf32(float* c, const uint32_t* a, const uint32_t* b) {
    asm volatile("mma.sync.aligned.m16n8k8.row.col.f32.tf32.tf32.f32 "
        "{%0,%1,%2,%3}, {%4,%5,%6,%7}, {%8,%9}, {%0,%1,%2,%3};"
        : "+f"(c[0]), "+f"(c[1]), "+f"(c[2]), "+f"(c[3])
        : "r"(a[0]), "r"(a[1]), "r"(a[2]), "r"(a[3]), "r"(b[0]), "r"(b[1]));
}
__device__ __forceinline__ float tf32r(float x) {
    uint32_t o;
    asm("cvt.rna.tf32.f32 %0, %1;" : "=r"(o) : "f"(x));
    return __uint_as_float(o);
}
__device__ __forceinline__ uint32_t tf32u(float x) {
    uint32_t o;
    asm("cvt.rna.tf32.f32 %0, %1;" : "=r"(o) : "f"(x));
    return o;
}

// FMA-pipe exp
__device__ __forceinline__ float fast_exp(float x) {
    x = fmaxf(x, -80.f);
    const float y = x * 1.4426950408889634f;
    const float fn = y + 12582912.f;
    const int ni = __float_as_int(fn) - 0x4B400000;
    const float f = y - (fn - 12582912.f);
    float p = 1.3333558146e-3f;
    p = fmaf(p, f, 9.6181291076e-3f);
    p = fmaf(p, f, 5.5504108664e-2f);
    p = fmaf(p, f, 2.4022650696e-1f);
    p = fmaf(p, f, 6.9314718056e-1f);
    p = fmaf(p, f, 1.0f);
    return p * __int_as_float((ni + 127) << 23);
}

// ---------------------------------------------------------------------------
// tf32 single-pass GEMM, split-K S slices: raw fp32 A & W, in-reg tf32 round.
// 128x256 CTA tile, BK=32 floats, double-buffered cp.async.
// smem row = 32 floats + 4 pad (144B). grid (M/128, Npad/256, S)
// ---------------------------------------------------------------------------
#define NF32 36    // floats per smem row
#define A_F  4608  // floats per A tile (128*36)
#define B_F  9216  // floats per B tile (256*36)
#define GSMEM_TOTAL ((2 * A_F + 2 * B_F) * 4)    // 110592

__device__ __forceinline__ void fill_tiles_tf32(
    uint32_t aT, uint32_t bT,
    const float* __restrict__ A, const float* __restrict__ W,
    int K, int m0, int n0, int k0, int Nrows, int tid)
{
    #pragma unroll
    for (int i = 0; i < 4; i++) {
        int q = tid + 256 * i;
        int r = q >> 3, c = q & 7;
        cp16(aT + r * 144 + c * 16, A + (size_t)(m0 + r) * K + k0 + c * 4);
    }
    #pragma unroll
    for (int i = 0; i < 8; i++) {
        int q = tid + 256 * i;
        int r = q >> 3, c = q & 7;
        int rw = n0 + r; if (rw >= Nrows) rw = Nrows - 1;
        cp16(bT + r * 144 + c * 16, W + (size_t)rw * K + k0 + c * 4);
    }
}

__global__ __launch_bounds__(256) void tf32_gemm_sk(
    const float* __restrict__ A, const float* __restrict__ W,
    float* __restrict__ ws, int K, int Npad, int Nrows, int S)
{
    extern __shared__ char smem[];
    const uint32_t sbase = smem_u32(smem);
    const uint32_t tA[2] = { sbase,               sbase + A_F * 4 };
    const uint32_t tB[2] = { sbase + 2 * A_F * 4, sbase + 2 * A_F * 4 + B_F * 4 };
    float* smf = (float*)smem;

    const int tid  = threadIdx.x;
    const int wid  = tid >> 5;
    const int lane = tid & 31;
    const int wm   = wid >> 2;
    const int wn   = wid & 3;
    const int g    = lane >> 2;
    const int qd   = lane & 3;
    const int m0 = blockIdx.x * 128;
    const int n0 = blockIdx.y * 256;
    const int z  = blockIdx.z;
    const int NC = K >> 5;
    const int cb = (z * NC) / S;
    const int ce = ((z + 1) * NC) / S;

    float acc[4][8][4];
    #pragma unroll
    for (int i = 0; i < 4; i++)
        #pragma unroll
        for (int j = 0; j < 8; j++)
            #pragma unroll
            for (int q = 0; q < 4; q++) acc[i][j][q] = 0.f;

    fill_tiles_tf32(tA[0], tB[0], A, W, K, m0, n0, cb << 5, Nrows, tid);
    cp_commit();

    for (int c = cb; c < ce; c++) {
        const int b = (c - cb) & 1;
        if (c + 1 < ce) {
            const int nb = (c + 1 - cb) & 1;
            fill_tiles_tf32(tA[nb], tB[nb], A, W, K, m0, n0,
                            (c + 1) << 5, Nrows, tid);
            cp_commit();
            cp_wait1();
        } else {
            cp_wait0();
        }
        __syncthreads();

        const float* As = smf + b * A_F;
        const float* Bs = smf + 2 * A_F + b * B_F;

        #pragma unroll
        for (int ks = 0; ks < 4; ks++) {
            const int k0 = ks * 8;
            uint32_t a[4][4], bb[8][2];
            #pragma unroll
            for (int mf = 0; mf < 4; mf++) {
                const int row = wm * 64 + mf * 16 + g;
                a[mf][0] = tf32u(As[row * NF32 + k0 + qd]);
                a[mf][1] = tf32u(As[(row + 8) * NF32 + k0 + qd]);
                a[mf][2] = tf32u(As[row * NF32 + k0 + 4 + qd]);
                a[mf][3] = tf32u(As[(row + 8) * NF32 + k0 + 4 + qd]);
            }
            #pragma unroll
            for (int nf = 0; nf < 8; nf++) {
                const int rowb = wn * 64 + nf * 8 + g;
                bb[nf][0] = tf32u(Bs[rowb * NF32 + k0 + qd]);
                bb[nf][1] = tf32u(Bs[rowb * NF32 + k0 + 4 + qd]);
            }
            #pragma unroll
            for (int mf = 0; mf < 4; mf++)
                #pragma unroll
                for (int nf = 0; nf < 8; nf++)
                    mma_tf32(acc[mf][nf], a[mf], bb[nf]);
        }
        __syncthreads();
    }

    float* wz = ws + (size_t)z * T_TOK * Npad;
    const int t = lane & 3;
    #pragma unroll
    for (int nf = 0; nf < 8; nf++) {
        const int col = n0 + wn * 64 + nf * 8 + t * 2;
        #pragma unroll
        for (int mf = 0; mf < 4; mf++) {
            const int r0 = m0 + wm * 64 + mf * 16 + g;
            *(float2*)(wz + (size_t)r0 * Npad + col) =
                make_float2(acc[mf][nf][0], acc[mf][nf][1]);
            *(float2*)(wz + (size_t)(r0 + 8) * Npad + col) =
                make_float2(acc[mf][nf][2], acc[mf][nf][3]);
        }
    }
}

// ---------------------------------------------------------------------------
// Rope table
// ---------------------------------------------------------------------------
__global__ void rope_table_kernel(float* __restrict__ tab)
{
    const int t = blockIdx.x;
    const int i = threadIdx.x;
    const float PI = 3.14159265358979323846f;
    const float rope_base = 150000.f;
    const float freq = powf(rope_base, (float)i / 32.f);
    const float conc = 0.1f * logf(32.f) + 1.f;
    const float lg = logf(rope_base);
    const float low  = 32.f * logf(4096.f / (32.f * 2.f * PI)) / lg;
    const float high = 32.f * logf(4096.f / (2.f * PI)) / lg;
    const float interp = 1.f / (32.f * freq);
    const float extrap = 1.f / freq;
    float ramp = ((float)i - low) / (high - low);
    ramp = fminf(fmaxf(ramp, 0.f), 1.f);
    const float mask = 1.f - ramp;
    const float invf = interp * (1.f - mask) + extrap * mask;
    const float ang = (float)t * invf;
    tab[t * 64 + i]      = cosf(ang) * conc;
    tab[t * 64 + 32 + i] = sinf(ang) * conc;
}

// ---------------------------------------------------------------------------
// RMSNorm (plain fp32 output)
// ---------------------------------------------------------------------------
__global__ __launch_bounds__(256) void rmsnorm_kernel(
    const float* __restrict__ x, const float* __restrict__ scale,
    float* __restrict__ out)
{
    const int row = blockIdx.x;
    const float* xr = x + (size_t)row * HID;
    float s = 0.f;
    for (int i = threadIdx.x; i < HID; i += 256) { float v = xr[i]; s += v * v; }
    __shared__ float red[256];
    red[threadIdx.x] = s;
    __syncthreads();
    for (int off = 128; off > 0; off >>= 1) {
        if (threadIdx.x < off) red[threadIdx.x] += red[threadIdx.x + off];
        __syncthreads();
    }
    const float inv = rsqrtf(red[0] / (float)HID + EPSF);
    float* orow = out + (size_t)row * HID;
    for (int i = threadIdx.x; i < HID; i += 256)
        orow[i] = xr[i] * inv * scale[i];
}

// ---------------------------------------------------------------------------
// QKV reduce (6 slices) + bias + RoPE -> qkv
// ---------------------------------------------------------------------------
__global__ __launch_bounds__(256) void reduce_qkv_rope_kernel(
    const float* __restrict__ ws, const float* __restrict__ bias,
    const float* __restrict__ tab, float* __restrict__ qkv)
{
    const int t = blockIdx.x;
    const int tid = threadIdx.x;
    const size_t SL = (size_t)T_TOK * QKV_DIM;
    const float* base = ws + (size_t)t * QKV_DIM;
    float* outr = qkv + (size_t)t * QKV_DIM;
    const float* tr = tab + t * 64;

    for (int p = tid; p < 72 * 32; p += 256) {
        const int head = p >> 5, d = p & 31;
        const int c1 = head * 64 + d, c2 = c1 + 32;
        float s1 = bias[c1], s2 = bias[c2];
        #pragma unroll
        for (int z = 0; z < 6; z++) {
            s1 += base[z * SL + c1];
            s2 += base[z * SL + c2];
        }
        const float cc = tr[d], ss = tr[32 + d];
        outr[c1] = s1 * cc - s2 * ss;
        outr[c2] = s2 * cc + s1 * ss;
    }
    for (int c = 4608 + tid; c < QKV_DIM; c += 256) {
        float s = bias[c];
        #pragma unroll
        for (int z = 0; z < 6; z++) s += base[z * SL + c];
        outr[c] = s;
    }
}

// ---------------------------------------------------------------------------
// out reduce (3) + bias + residual -> h, then rmsnorm -> fp32 g_t
// ---------------------------------------------------------------------------
__global__ __launch_bounds__(256) void reduce_out_rms_kernel(
    const float* __restrict__ ws, const float* __restrict__ bias,
    const float* __restrict__ res, const float* __restrict__ scale,
    float* __restrict__ h, float* __restrict__ tn)
{
    __shared__ float row[HID];
    __shared__ float red[256];
    const int t = blockIdx.x;
    const int tid = threadIdx.x;
    const size_t SL = (size_t)T_TOK * NPAD_OUT;
    const float* base = ws + (size_t)t * NPAD_OUT;
    const float* xr = res + (size_t)t * HID;
    float* hr = h + (size_t)t * HID;

    float sq = 0.f;
    for (int c = tid * 4; c < HID; c += 1024) {
        const float4 a = *(const float4*)(base + c);
        const float4 b = *(const float4*)(base + SL + c);
        const float4 d = *(const float4*)(base + 2 * SL + c);
        const float4 bb = *(const float4*)(bias + c);
        const float4 rv = *(const float4*)(xr + c);
        float4 v;
        v.x = a.x + b.x + d.x + bb.x + rv.x;
        v.y = a.y + b.y + d.y + bb.y + rv.y;
        v.z = a.z + b.z + d.z + bb.z + rv.z;
        v.w = a.w + b.w + d.w + bb.w + rv.w;
        *(float4*)(row + c) = v;
        *(float4*)(hr + c) = v;
        sq += v.x * v.x + v.y * v.y + v.z * v.z + v.w * v.w;
    }
    red[tid] = sq;
    __syncthreads();
    for (int off = 128; off > 0; off >>= 1) {
        if (tid < off) red[tid] += red[tid + off];
        __syncthreads();
    }
    const float inv = rsqrtf(red[0] / (float)HID + EPSF);
    float* tr = tn + (size_t)t * HID;
    for (int c = tid * 4; c < HID; c += 1024) {
        float4 v = *(const float4*)(row + c);
        float4 sc = *(const float4*)(scale + c);
        v.x *= inv * sc.x; v.y *= inv * sc.y;
        v.z *= inv * sc.z; v.w *= inv * sc.w;
        *(float4*)(tr + c) = v;
    }
}

// ---------------------------------------------------------------------------
// up reduce (3) + bias + clamped SwiGLU -> fp32 g_act
// ---------------------------------------------------------------------------
__global__ __launch_bounds__(256) void reduce_up_act_kernel(
    const float* __restrict__ ws, const float* __restrict__ bias,
    float* __restrict__ act)
{
    const int t = blockIdx.y;
    const int j = blockIdx.x * 256 + threadIdx.x;   // 0..1439
    if (j >= INTER / 2) return;
    const int c = j * 4;
    const size_t SL = (size_t)T_TOK * NPAD_UP;
    const float* base = ws + (size_t)t * NPAD_UP + c;
    const float4 a = *(const float4*)base;
    const float4 b = *(const float4*)(base + SL);
    const float4 d = *(const float4*)(base + 2 * SL);
    const float4 bb = *(const float4*)(bias + c);
    float u0 = a.x + b.x + d.x + bb.x;
    float u1 = a.y + b.y + d.y + bb.y;
    float u2 = a.z + b.z + d.z + bb.z;
    float u3 = a.w + b.w + d.w + bb.w;

    float g0 = fminf(u0, 7.f), l0 = fminf(fmaxf(u1, -7.f), 7.f);
    float g1 = fminf(u2, 7.f), l1 = fminf(fmaxf(u3, -7.f), 7.f);
    const float v0 = g0 / (1.f + fast_exp(-1.702f * g0)) * (l0 + 1.f);
    const float v1 = g1 / (1.f + fast_exp(-1.702f * g1)) * (l1 + 1.f);

    *(float2*)(act + (size_t)t * INTER + 2 * j) = make_float2(v0, v1);
}

// ---------------------------------------------------------------------------
// dn reduce (3) + bias + residual -> out (final)
// ---------------------------------------------------------------------------
__global__ __launch_bounds__(256) void reduce_dn_kernel(
    const float* __restrict__ ws, const float* __restrict__ bias,
    const float* __restrict__ res, float* __restrict__ C)
{
    const int idx = blockIdx.x * 256 + threadIdx.x;
    const int q = HID >> 2;
    if (idx >= T_TOK * q) return;
    const int m = idx / q;
    const int col = (idx - m * q) * 4;
    const size_t SL = (size_t)T_TOK * NPAD_DN;
    const float* p = ws + (size_t)m * NPAD_DN + col;
    const float4 a = *(const float4*)p;
    const float4 b = *(const float4*)(p + SL);
    const float4 c = *(const float4*)(p + 2 * SL);
    const float4 bb = *(const float4*)(bias + col);
    const float4 r = *(const float4*)(res + (size_t)m * HID + col);
    float4 v;
    v.x = a.x + b.x + c.x + bb.x + r.x;
    v.y = a.y + b.y + c.y + bb.y + r.y;
    v.z = a.z + b.z + c.z + bb.z + r.z;
    v.w = a.w + b.w + c.w + bb.w + r.w;
    *(float4*)(C + (size_t)m * HID + col) = v;
}

// ---------------------------------------------------------------------------
// Causal GQA flash attention (tf32 mma + FMA-pipe exp), fp32 output
// ---------------------------------------------------------------------------
#define ATQ 68
#define ATV 72
#define ATTN_SMEM ((3 * 64 * ATQ + 64 * ATV + 3 * 64 + 2 * 256) * (int)sizeof(float))

__global__ __launch_bounds__(256) void attn_mma_kernel(
    const float* __restrict__ qkv, float* __restrict__ og)
{
    extern __shared__ float sm[];
    float* Qs   = sm;
    float* Ks   = Qs + 64 * ATQ;
    float* Ss   = Ks + 64 * ATQ;
    float* Vs   = Ss + 64 * ATQ;
    float* mrow = Vs + 64 * ATV;
    float* lrow = mrow + 64;
    float* arow = lrow + 64;
    float* pm   = arow + 64;
    float* ps   = pm + 256;

    const int qt = blockIdx.x, h = blockIdx.y, kh = h >> 3;
    const int tid = threadIdx.x, wid = tid >> 5, lane = tid & 31;
    const int wm = wid >> 2, wn = wid & 3;
    const int g = lane >> 2, qd = lane & 3;
    const int sr = tid & 63, sq = tid >> 6;

    for (int i = tid; i < 64 * 64; i += 256) {
        int r = i >> 6, d = i & 63;
        Qs[r * ATQ + d] = tf32r(qkv[(size_t)(qt * 64 + r) * QKV_DIM + h * HD + d]);
    }
    if (tid < 64) { mrow[tid] = -1e30f; lrow[tid] = 0.f; }
    float o[2][2][4];
    #pragma unroll
    for (int i = 0; i < 2; i++)
        #pragma unroll
        for (int j = 0; j < 2; j++)
            #pragma unroll
            for (int q = 0; q < 4; q++) o[i][j][q] = 0.f;
    __syncthreads();

    for (int kt = 0; kt <= qt; kt++) {
        for (int i = tid; i < 64 * 64; i += 256) {
            int r = i >> 6, d = i & 63;
            size_t base = (size_t)(kt * 64 + r) * QKV_DIM;
            Ks[r * ATQ + d] = tf32r(qkv[base + NH * HD + kh * HD + d]);
            Vs[r * ATV + d] = tf32r(qkv[base + (NH + KVH) * HD + kh * HD + d]);
        }
        __syncthreads();

        float s[2][2][4];
        #pragma unroll
        for (int i = 0; i < 2; i++)
            #pragma unroll
            for (int j = 0; j < 2; j++)
                #pragma unroll
                for (int q = 0; q < 4; q++) s[i][j][q] = 0.f;
        #pragma unroll
        for (int k8 = 0; k8 < 8; k8++) {
            const int k0 = k8 * 8;
            uint32_t a[2][4], b[2][2];
            #pragma unroll
            for (int mf = 0; mf < 2; mf++) {
                const int rb = wm * 32 + mf * 16;
                a[mf][0] = __float_as_uint(Qs[(rb + g) * ATQ + k0 + qd]);
                a[mf][1] = __float_as_uint(Qs[(rb + g + 8) * ATQ + k0 + qd]);
                a[mf][2] = __float_as_uint(Qs[(rb + g) * ATQ + k0 + 4 + qd]);
                a[mf][3] = __float_as_uint(Qs[(rb + g + 8) * ATQ + k0 + 4 + qd]);
            }
            #pragma unroll
            for (int nf = 0; nf < 2; nf++) {
                const int nb = wn * 16 + nf * 8;
                b[nf][0] = __float_as_uint(Ks[(nb + g) * ATQ + k0 + qd]);
                b[nf][1] = __float_as_uint(Ks[(nb + g) * ATQ + k0 + 4 + qd]);
            }
            #pragma unroll
            for (int mf = 0; mf < 2; mf++)
                #pragma unroll
                for (int nf = 0; nf < 2; nf++)
                    mma_tf32(s[mf][nf], a[mf], b[nf]);
        }
        #pragma unroll
        for (int mf = 0; mf < 2; mf++)
            #pragma unroll
            for (int nf = 0; nf < 2; nf++) {
                const int r0 = wm * 32 + mf * 16 + g;
                const int c0 = wn * 16 + nf * 8 + 2 * qd;
                *(float2*)&Ss[r0 * ATQ + c0] =
                    make_float2(s[mf][nf][0] * SM_SCALE, s[mf][nf][1] * SM_SCALE);
                *(float2*)&Ss[(r0 + 8) * ATQ + c0] =
                    make_float2(s[mf][nf][2] * SM_SCALE, s[mf][nf][3] * SM_SCALE);
            }
        __syncthreads();

        {
            const int cmax = (kt == qt) ? (sr + 1) : 64;
            const int c0 = sq * 16;
            float mx = -1e30f;
            #pragma unroll
            for (int c = c0; c < c0 + 16; c++)
                if (c < cmax) mx = fmaxf(mx, Ss[sr * ATQ + c]);
            pm[sq * 64 + sr] = mx;
            __syncthreads();
            const float mold = mrow[sr];
            const float mfin = fmaxf(mold,
                fmaxf(fmaxf(pm[sr], pm[64 + sr]), fmaxf(pm[128 + sr], pm[192 + sr])));
            float sum = 0.f;
            #pragma unroll
            for (int c = c0; c < c0 + 16; c++) {
                float p = (c < cmax) ? fast_exp(Ss[sr * ATQ + c] - mfin) : 0.f;
                Ss[sr * ATQ + c] = tf32r(p);
                sum += p;
            }
            ps[sq * 64 + sr] = sum;
            __syncthreads();
            if (sq == 0) {
                const float alpha = fast_exp(mold - mfin);
                mrow[sr] = mfin;
                lrow[sr] = lrow[sr] * alpha
                         + ps[sr] + ps[64 + sr] + ps[128 + sr] + ps[192 + sr];
                arow[sr] = alpha;
            }
            __syncthreads();
        }

        #pragma unroll
        for (int mf = 0; mf < 2; mf++) {
            const int r0 = wm * 32 + mf * 16 + g;
            const float al0 = arow[r0], al1 = arow[r0 + 8];
            #pragma unroll
            for (int nf = 0; nf < 2; nf++) {
                o[mf][nf][0] *= al0; o[mf][nf][1] *= al0;
                o[mf][nf][2] *= al1; o[mf][nf][3] *= al1;
            }
        }
        #pragma unroll
        for (int k8 = 0; k8 < 8; k8++) {
            const int k0 = k8 * 8;
            uint32_t a[2][4], b[2][2];
            #pragma unroll
            for (int mf = 0; mf < 2; mf++) {
                const int rb = wm * 32 + mf * 16;
                a[mf][0] = __float_as_uint(Ss[(rb + g) * ATQ + k0 + qd]);
                a[mf][1] = __float_as_uint(Ss[(rb + g + 8) * ATQ + k0 + qd]);
                a[mf][2] = __float_as_uint(Ss[(rb + g) * ATQ + k0 + 4 + qd]);
                a[mf][3] = __float_as_uint(Ss[(rb + g + 8) * ATQ + k0 + 4 + qd]);
            }
            #pragma unroll
            for (int nf = 0; nf < 2; nf++) {
                const int nb = wn * 16 + nf * 8;
                b[nf][0] = __float_as_uint(Vs[(k0 + qd) * ATV + nb + g]);
                b[nf][1] = __float_as_uint(Vs[(k0 + 4 + qd) * ATV + nb + g]);
            }
            #pragma unroll
            for (int mf = 0; mf < 2; mf++)
                #pragma unroll
                for (int nf = 0; nf < 2; nf++)
                    mma_tf32(o[mf][nf], a[mf], b[nf]);
        }
        __syncthreads();
    }

    #pragma unroll
    for (int mf = 0; mf < 2; mf++) {
        const int r0 = wm * 32 + mf * 16 + g;
        const float li0 = 1.f / lrow[r0];
        const float li1 = 1.f / lrow[r0 + 8];
        #pragma unroll
        for (int nf = 0; nf < 2; nf++) {
            const int col = h * HD + wn * 16 + nf * 8 + 2 * qd;
            *(float2*)(og + (size_t)(qt * 64 + r0) * O_DIM + col) =
                make_float2(o[mf][nf][0] * li0, o[mf][nf][1] * li0);
            *(float2*)(og + (size_t)(qt * 64 + r0 + 8) * O_DIM + col) =
                make_float2(o[mf][nf][2] * li1, o[mf][nf][3] * li1);
        }
    }
}

// ---------------------------------------------------------------------------
// Launch
// ---------------------------------------------------------------------------
static inline int cdiv_i(long long a, int b) { return (int)((a + b - 1) / b); }

extern "C" void kernel_launch(void* const* d_in, const int* in_sizes, int n_in,
                              void* d_out, int out_size)
{
    const float* x        = (const float*)d_in[0];
    const float* an_scale = (const float*)d_in[1];
    const float* wqkv     = (const float*)d_in[2];
    const float* bqkv     = (const float*)d_in[3];
    const float* wout     = (const float*)d_in[4];
    const float* bout     = (const float*)d_in[5];
    const float* mn_scale = (const float*)d_in[6];
    const float* w1       = (const float*)d_in[7];
    const float* b1       = (const float*)d_in[8];
    const float* w2       = (const float*)d_in[9];
    const float* b2       = (const float*)d_in[10];
    float* out = (float*)d_out;

    static float *qkv_p = nullptr, *h_p, *t_p, *o_p, *act_p, *ws_p, *rt_p;
    if (!qkv_p) {
        cudaGetSymbolAddress((void**)&qkv_p,  g_qkv);
        cudaGetSymbolAddress((void**)&h_p,    g_h);
        cudaGetSymbolAddress((void**)&t_p,    g_t);
        cudaGetSymbolAddress((void**)&o_p,    g_o);
        cudaGetSymbolAddress((void**)&act_p,  g_act);
        cudaGetSymbolAddress((void**)&ws_p,   g_ws);
        cudaGetSymbolAddress((void**)&rt_p,   g_rope);
    }
    cudaFuncSetAttribute(attn_mma_kernel,
                         cudaFuncAttributeMaxDynamicSharedMemorySize, ATTN_SMEM);
    cudaFuncSetAttribute(tf32_gemm_sk,
                         cudaFuncAttributeMaxDynamicSharedMemorySize, GSMEM_TOTAL);

    // rope table
    rope_table_kernel<<<T_TOK, 32>>>(rt_p);

    // 1) attn rmsnorm -> fp32 t
    rmsnorm_kernel<<<T_TOK, 256>>>(x, an_scale, t_p);

    // 2) QKV GEMM (tf32 single pass, S=6) + fused reduce+rope
    {
        dim3 grid(T_TOK / 128, QKV_DIM / 256, 6);
        tf32_gemm_sk<<<grid, 256, GSMEM_TOTAL>>>(t_p, wqkv, ws_p,
                                                 HID, QKV_DIM, QKV_DIM, 6);
        reduce_qkv_rope_kernel<<<T_TOK, 256>>>(ws_p, bqkv, rt_p, qkv_p);
    }

    // 3) attention -> fp32 o
    {
        dim3 grid(T_TOK / 64, NH);
        attn_mma_kernel<<<grid, 256, ATTN_SMEM>>>(qkv_p, o_p);
    }

    // 4) out GEMM (tf32, S=3) + fused reduce+residual+rmsnorm
    {
        dim3 grid(T_TOK / 128, NPAD_OUT / 256, 3);
        tf32_gemm_sk<<<grid, 256, GSMEM_TOTAL>>>(o_p, wout, ws_p,
                                                 O_DIM, NPAD_OUT, HID, 3);
        reduce_out_rms_kernel<<<T_TOK, 256>>>(ws_p, bout, x, mn_scale, h_p, t_p);
    }

    // 5) MLP up GEMM (tf32, S=3) + fused reduce+act
    {
        dim3 grid(T_TOK / 128, NPAD_UP / 256, 3);
        tf32_gemm_sk<<<grid, 256, GSMEM_TOTAL>>>(t_p, w1, ws_p,
                                                 HID, NPAD_UP, U_DIM, 3);
        dim3 rg(cdiv_i(INTER / 2, 256), T_TOK);
        reduce_up_act_kernel<<<rg, 256>>>(ws_p, b1, act_p);
    }

    // 6) MLP down GEMM (tf32, S=3) + fused reduce+residual -> out
    {
        dim3 grid(T_TOK / 128, NPAD_DN / 256, 3);
        tf32_gemm_sk<<<grid, 256, GSMEM_TOTAL>>>(act_p, w2, ws_p,
                                                 INTER, NPAD_DN, HID, 3);
        reduce_dn_kernel<<<cdiv_i((long long)T_TOK * HID / 4, 256), 256>>>(
            ws_p, b2, h_p, out);
    }
}